// round 8
// baseline (speedup 1.0000x reference)
#include <cuda_runtime.h>
#include <cuda_fp16.h>
#include <cstdint>

#define T_ 65536
#define D_ 256
#define CHUNK 128
#define NCH (T_/CHUNK)   // 512

// ================= device scratch (no allocations allowed) =================
__device__ float g_af [T_*D_];
__device__ float g_bf [T_*D_];
__device__ float g_ab2[T_*D_];
__device__ float g_bb2[T_*D_];
__device__ float g_cA [2*NCH*D_];
__device__ float g_cB [2*NCH*D_];
__device__ float g_pref[2*NCH*D_];
__device__ float g_hbias[2][D_];        // layer0: bh + q0 @ Wh_bottom

__device__ __half g_xhi[T_*D_], g_xlo[T_*D_];
__device__ __half g_uhi[T_*D_], g_ulo[T_*D_];
__device__ __half g_qhi[T_*D_], g_qlo[T_*D_];
__device__ __half g_wzT[5][D_*D_];      // [layerdir][n*256+k]
__device__ __half g_whT[5][D_*2*D_];    // [layerdir][n*512+k]

// ================= helpers =================
__device__ __forceinline__ uint32_t smem_u32(const void* p) {
    uint32_t a;
    asm("{ .reg .u64 t; cvta.to.shared.u64 t, %1; cvt.u32.u64 %0, t; }" : "=r"(a) : "l"(p));
    return a;
}
__device__ __forceinline__ void ldsm_x4(uint32_t (&r)[4], uint32_t addr) {
    asm volatile("ldmatrix.sync.aligned.m8n8.x4.shared.b16 {%0,%1,%2,%3}, [%4];"
                 : "=r"(r[0]), "=r"(r[1]), "=r"(r[2]), "=r"(r[3]) : "r"(addr));
}
__device__ __forceinline__ void mma16816(float (&d)[4], const uint32_t (&a)[4], const uint32_t* b) {
    asm volatile("mma.sync.aligned.m16n8k16.row.col.f32.f16.f16.f32 "
                 "{%0,%1,%2,%3}, {%4,%5,%6,%7}, {%8,%9}, {%0,%1,%2,%3};"
                 : "+f"(d[0]), "+f"(d[1]), "+f"(d[2]), "+f"(d[3])
                 : "r"(a[0]), "r"(a[1]), "r"(a[2]), "r"(a[3]), "r"(b[0]), "r"(b[1]));
}
__device__ __forceinline__ void cpa16(uint32_t dst, const void* src) {
    asm volatile("cp.async.cg.shared.global [%0], [%1], 16;" :: "r"(dst), "l"(src));
}
#define CP_COMMIT() asm volatile("cp.async.commit_group;" ::: "memory")
#define CP_WAIT1()  asm volatile("cp.async.wait_group 1;" ::: "memory")

__device__ __forceinline__ float sigf(float v)   { return 1.0f/(1.0f+__expf(-v)); }
__device__ __forceinline__ float tanhf_(float v) { return 1.0f - 2.0f/(__expf(2.0f*v)+1.0f); }
__device__ __forceinline__ void split2h(float v, __half& h, __half& l) {
    h = __float2half_rn(v);
    l = __float2half_rn(v - __half2float(h));
}

// ================= prep kernels =================
__global__ void prep_w(const float* __restrict__ Wz, const float* __restrict__ Wh, int ld)
{
    int mz = blockIdx.z;
    if (mz == 0 && blockIdx.y >= 8) return;
    const float* src = mz ? Wh : Wz;
    int Krows = mz ? 512 : 256;
    __half* dh = mz ? &g_whT[ld][0] : &g_wzT[ld][0];
    int k0 = blockIdx.y*32, n0 = blockIdx.x*32;
    int tx = threadIdx.x, ty = threadIdx.y;
    __shared__ float t[32][33];
    #pragma unroll
    for (int i = 0; i < 4; i++)
        t[ty + i*8][tx] = src[(size_t)(k0 + ty + i*8)*256 + n0 + tx];
    __syncthreads();
    #pragma unroll
    for (int i = 0; i < 4; i++)
        dh[(size_t)(n0 + ty + i*8)*Krows + k0 + tx] = __float2half_rn(t[tx][ty + i*8]);
}

__global__ void prep_xu(const float* __restrict__ story, const float* __restrict__ q)
{
    size_t i = ((size_t)blockIdx.x*256 + threadIdx.x)*2;
    int d = (int)(i & (D_-1));
    float2 v = *(const float2*)(story + i);
    __half h0,l0,h1,l1;
    split2h(v.x,h0,l0); split2h(v.y,h1,l1);
    __half2 ph, pl; ph.x=h0; ph.y=h1; pl.x=l0; pl.y=l1;
    *(__half2*)(g_xhi+i) = ph; *(__half2*)(g_xlo+i) = pl;
    float u0 = v.x * q[d], u1 = v.y * q[d+1];
    split2h(u0,h0,l0); split2h(u1,h1,l1);
    ph.x=h0; ph.y=h1; pl.x=l0; pl.y=l1;
    *(__half2*)(g_uhi+i) = ph; *(__half2*)(g_ulo+i) = pl;
}

// warp-per-(dir,n): hbias[dir][n] = bh[n] + sum_k q[k]*Wh[(256+k)*256+n]
__global__ void qwh0(const float* __restrict__ Whf, const float* __restrict__ bhf,
                     const float* __restrict__ Whb, const float* __restrict__ bhb,
                     const float* __restrict__ q)
{
    int gw = (blockIdx.x * blockDim.x + threadIdx.x) >> 5;
    int lane = threadIdx.x & 31;
    int dir = gw >> 8, n = gw & 255;
    const float* Wh = dir ? Whb : Whf;
    const float* bh = dir ? bhb : bhf;
    float acc = 0.f;
    #pragma unroll
    for (int kk = 0; kk < 8; kk++) {
        int k = kk*32 + lane;
        acc = fmaf(q[k], Wh[(size_t)(256+k)*256 + n], acc);
    }
    #pragma unroll
    for (int o = 16; o; o >>= 1) acc += __shfl_xor_sync(0xFFFFFFFFu, acc, o);
    if (lane == 0) g_hbias[dir][n] = bh[n] + acc;
}

// ================= fused GEMM (mma.sync fp16 2-pass, N=256, 512 threads) =================
// CTA: M=128 (one chunk) x N=256 (all channels). 16 warps = 4M x 4N.
// Stage (40960B): Ahi [0,10240) | Alo [10240,20480) | B [20480,40960)  (strides 40 halves)
// Dynamic SMEM: 2 stages (81920) + zbuf fp32 128x264 (135168) = 217088.
// Post-mainloop the stage area is reused as a/b quarter buffers (128x68 fp32 each).
#define STAGE_B 40960
#define ZBUF_OFF (2*STAGE_B)
#define SM_GEMM (ZBUF_OFF + 135168)
#define TSTR 40

__device__ __forceinline__ void issue_stage(int s, uint32_t sb, int row0,
    const __half* wz, const __half* wh, int tid)
{
    const __half *Ah, *Al, *B; int ka, kb, Kd;
    if (s < 8)       { Ah=g_uhi; Al=g_ulo; B=wz; ka=s*32;      kb=s*32;     Kd=256; }
    else if (s < 16) { Ah=g_xhi; Al=g_xlo; B=wh; ka=(s-8)*32;  kb=(s-8)*32; Kd=512; }
    else             { Ah=g_qhi; Al=g_qlo; B=wh; ka=(s-16)*32; kb=(s-8)*32; Kd=512; }
    #pragma unroll
    for (int i = 0; i < 4; i++) {
        int v = tid + i*512;              // 0..2047
        if (v < 1024) {
            int t = v >> 9, c = v & 511, r = c >> 2, q = c & 3;
            const __half* sp = t ? Al : Ah;
            cpa16(sb + (uint32_t)(t*10240 + r*80 + q*16),
                  sp + (size_t)(row0 + r)*256 + ka + q*8);
        } else {
            int c = v - 1024, r = c >> 2, q = c & 3;
            cpa16(sb + (uint32_t)(20480 + r*80 + q*16),
                  B + (size_t)r*Kd + kb + q*8);
        }
    }
}

__device__ __forceinline__ void mma_step(float (&acc)[2][8][4],
    uint32_t stg, int wm, int wn, int lane)
{
    const uint32_t uA = stg, uB = stg + 20480;
    #pragma unroll
    for (int kk = 0; kk < 32; kk += 16) {
        uint32_t aH[2][4], aL[2][4], bb[8][2];
        #pragma unroll
        for (int mi = 0; mi < 2; mi++) {
            uint32_t roff = (uint32_t)(wm*32 + mi*16 + (lane & 15))*(TSTR*2)
                          + (uint32_t)(kk + ((lane >> 4) << 3))*2;
            ldsm_x4(aH[mi], uA + roff);
            ldsm_x4(aL[mi], uA + 10240 + roff);
        }
        #pragma unroll
        for (int pi = 0; pi < 4; pi++) {
            uint32_t nrow = (uint32_t)(wn*64 + pi*16 + ((lane >> 4) << 3) + (lane & 7));
            uint32_t off = nrow*(TSTR*2) + (uint32_t)(kk + (((lane >> 3) & 1) << 3))*2;
            uint32_t t[4];
            ldsm_x4(t, uB + off);
            bb[pi*2][0]=t[0]; bb[pi*2][1]=t[1]; bb[pi*2+1][0]=t[2]; bb[pi*2+1][1]=t[3];
        }
        #pragma unroll
        for (int mi = 0; mi < 2; mi++)
            #pragma unroll
            for (int ni = 0; ni < 8; ni++) {
                mma16816(acc[mi][ni], aH[mi], bb[ni]);
                mma16816(acc[mi][ni], aL[mi], bb[ni]);
            }
    }
}

__global__ __launch_bounds__(512, 1)
void qrn_gemm(int ld_f, int ld_b, int layer0, int store_ab,
              const float* __restrict__ bz_f_, const float* __restrict__ bz_b_,
              const float* __restrict__ bh_f_, const float* __restrict__ bh_b_)
{
    extern __shared__ __align__(16) char smem[];
    float* zbuf = (float*)(smem + ZBUF_OFF);       // 128 x 264
    float* qAb  = (float*)smem;                    // quarter a: 128 x 68 (post-mainloop)
    float* qBb  = (float*)(smem + 34816);          // quarter b
    __shared__ float s_bz[256], s_bh[256];
    __shared__ float s_pA[8][64], s_pB[8][64];

    const int tid = threadIdx.x, lane = tid & 31, warp = tid >> 5;
    const int wm = warp & 3, wn = warp >> 2;
    const int ch = blockIdx.x, dir = blockIdx.z;
    const int ld = dir ? ld_b : ld_f;
    const int row0 = ch*CHUNK;
    const uint32_t base = smem_u32(smem);

    if (tid < 256) {
        s_bz[tid] = (dir ? bz_b_ : bz_f_)[tid];
        s_bh[tid] = layer0 ? g_hbias[dir][tid] : (dir ? bh_b_ : bh_f_)[tid];
    }

    const __half* wz = &g_wzT[ld][0];
    const __half* wh = &g_whT[ld][0];
    const int S = layer0 ? 16 : 24;

    float acc[2][8][4];
    #pragma unroll
    for (int mi = 0; mi < 2; mi++)
        #pragma unroll
        for (int ni = 0; ni < 8; ni++)
            #pragma unroll
            for (int j = 0; j < 4; j++) acc[mi][ni][j] = 0.f;

    issue_stage(0, base, row0, wz, wh, tid);
    CP_COMMIT();

    for (int s = 0; s < S; s++) {
        __syncthreads();   // all warps finished reading stage (s+1)&1 at step s-1
        if (s + 1 < S) issue_stage(s+1, base + ((s+1)&1)*STAGE_B, row0, wz, wh, tid);
        CP_COMMIT();
        CP_WAIT1();        // group s complete
        __syncthreads();   // stage s visible to all

        mma_step(acc, base + (s&1)*STAGE_B, wm, wn, lane);

        if (s == 7) {      // z epilogue -> zbuf, reset acc for H phase
            #pragma unroll
            for (int mi = 0; mi < 2; mi++) {
                int r0 = wm*32 + mi*16 + (lane >> 2);
                #pragma unroll
                for (int ni = 0; ni < 8; ni++) {
                    int cl = wn*64 + ni*8 + (lane & 3)*2;
                    zbuf[r0*264 + cl]     = sigf(acc[mi][ni][0] + s_bz[cl]);
                    zbuf[r0*264 + cl + 1] = sigf(acc[mi][ni][1] + s_bz[cl+1]);
                    zbuf[(r0+8)*264 + cl]     = sigf(acc[mi][ni][2] + s_bz[cl]);
                    zbuf[(r0+8)*264 + cl + 1] = sigf(acc[mi][ni][3] + s_bz[cl+1]);
                    #pragma unroll
                    for (int j = 0; j < 4; j++) acc[mi][ni][j] = 0.f;
                }
            }
        }
    }
    __syncthreads();   // mainloop done; stage area reusable as quarter buffers

    float* outA = dir ? g_ab2 : g_af;
    float* outB = dir ? g_bb2 : g_bf;

    // four 64-column quarters: epilogue + store + composites
    for (int qn = 0; qn < 4; qn++) {
        if (wn == qn) {
            #pragma unroll
            for (int mi = 0; mi < 2; mi++) {
                int r0 = wm*32 + mi*16 + (lane >> 2);
                #pragma unroll
                for (int ni = 0; ni < 8; ni++) {
                    int cl = ni*8 + (lane & 3)*2;     // 0..63 within quarter
                    int cg = qn*64 + cl;
                    #pragma unroll
                    for (int hrow = 0; hrow < 2; hrow++) {
                        int r = r0 + hrow*8;
                        float z0 = zbuf[r*264 + cg], z1 = zbuf[r*264 + cg + 1];
                        float h0 = tanhf_(acc[mi][ni][hrow*2+0] + s_bh[cg]);
                        float h1 = tanhf_(acc[mi][ni][hrow*2+1] + s_bh[cg+1]);
                        qAb[r*68 + cl]     = 1.0f - z0;
                        qAb[r*68 + cl + 1] = 1.0f - z1;
                        qBb[r*68 + cl]     = z0*h0;
                        qBb[r*68 + cl + 1] = z1*h1;
                    }
                }
            }
        }
        __syncthreads();

        if (store_ab) {
            #pragma unroll
            for (int i = 0; i < 4; i++) {
                int v = tid + i*512;          // 0..2047
                int r = v >> 4, c4 = (v & 15)*4;
                float4 va = *(float4*)(qAb + r*68 + c4);
                float4 vb = *(float4*)(qBb + r*68 + c4);
                size_t o = (size_t)(row0 + r)*256 + qn*64 + c4;
                *(float4*)(outA + o) = va;
                *(float4*)(outB + o) = vb;
            }
        }

        {   // per-seg composite partials (16 rows each), ordered by scan dir
            int cc = tid & 63, seg = tid >> 6;
            float pa = 1.0f, pb = 0.0f;
            if (dir == 0) {
                #pragma unroll 4
                for (int r = seg*16; r < seg*16 + 16; r++) {
                    float a = qAb[r*68 + cc], b = qBb[r*68 + cc];
                    pb = fmaf(a, pb, b); pa *= a;
                }
            } else {
                #pragma unroll 4
                for (int r = seg*16 + 15; r >= seg*16; r--) {
                    float a = qAb[r*68 + cc], b = qBb[r*68 + cc];
                    pb = fmaf(a, pb, b); pa *= a;
                }
            }
            s_pA[seg][cc] = pa; s_pB[seg][cc] = pb;
        }
        __syncthreads();
        if (tid < 64) {
            float A = 1.0f, B = 0.0f;
            if (dir == 0) {
                #pragma unroll
                for (int s = 0; s < 8; s++) { B = fmaf(s_pA[s][tid], B, s_pB[s][tid]); A *= s_pA[s][tid]; }
            } else {
                #pragma unroll
                for (int s = 7; s >= 0; s--) { B = fmaf(s_pA[s][tid], B, s_pB[s][tid]); A *= s_pA[s][tid]; }
            }
            size_t o = ((size_t)dir*NCH + ch)*256 + qn*64 + tid;
            g_cA[o] = A; g_cB[o] = B;
        }
        __syncthreads();
    }
}

// ================= scan kernels =================
__global__ __launch_bounds__(256) void scan_prefix()
{
    int dir = blockIdx.x, d = threadIdx.x;
    float cB = 0.f;
    if (dir == 0) {
        for (int c0 = 0; c0 < NCH; c0 += 8) {
            float a[8], b[8];
            #pragma unroll
            for (int i = 0; i < 8; i++) {
                a[i] = g_cA[(c0+i)*D_ + d];
                b[i] = g_cB[(c0+i)*D_ + d];
            }
            #pragma unroll
            for (int i = 0; i < 8; i++) {
                g_pref[(c0+i)*D_ + d] = cB;
                cB = fmaf(a[i], cB, b[i]);
            }
        }
    } else {
        for (int c0 = NCH - 8; c0 >= 0; c0 -= 8) {
            float a[8], b[8];
            #pragma unroll
            for (int i = 0; i < 8; i++) {
                a[i] = g_cA[(NCH + c0+i)*D_ + d];
                b[i] = g_cB[(NCH + c0+i)*D_ + d];
            }
            #pragma unroll
            for (int i = 7; i >= 0; i--) {
                g_pref[(NCH + c0+i)*D_ + d] = cB;
                cB = fmaf(a[i], cB, b[i]);
            }
        }
    }
}

// fused fwd+bwd apply + next-layer operand prep (h_fwd staged in smem)
__global__ __launch_bounds__(256) void scan_apply(const float* __restrict__ story)
{
    extern __shared__ float hbuf[];   // 128 x 256
    int d = threadIdx.x, ch = blockIdx.x;

    float h = g_pref[ch*D_ + d];
    size_t base = (size_t)ch*CHUNK*D_ + d;
    for (int j0 = 0; j0 < CHUNK; j0 += 8) {
        float a[8], b[8];
        #pragma unroll
        for (int i = 0; i < 8; i++) {
            size_t o = base + (size_t)(j0+i)*D_;
            a[i] = g_af[o]; b[i] = g_bf[o];
        }
        #pragma unroll
        for (int i = 0; i < 8; i++) {
            h = fmaf(a[i], h, b[i]);
            hbuf[(j0+i)*256 + d] = h;
        }
    }

    float h2 = g_pref[(NCH + ch)*D_ + d];
    size_t base2 = ((size_t)ch*CHUNK + CHUNK-1)*D_ + d;
    for (int j0 = 0; j0 < CHUNK; j0 += 8) {
        float a[8], b[8], x[8];
        #pragma unroll
        for (int i = 0; i < 8; i++) {
            size_t o = base2 - (size_t)(j0+i)*D_;
            a[i] = g_ab2[o]; b[i] = g_bb2[o]; x[i] = story[o];
        }
        #pragma unroll
        for (int i = 0; i < 8; i++) {
            size_t o = base2 - (size_t)(j0+i)*D_;
            h2 = fmaf(a[i], h2, b[i]);
            float q = hbuf[(CHUNK-1-(j0+i))*256 + d] + h2;
            float u = x[i] * q;
            __half qh, ql, uh, ul;
            split2h(q, qh, ql); split2h(u, uh, ul);
            g_qhi[o] = qh; g_qlo[o] = ql; g_uhi[o] = uh; g_ulo[o] = ul;
        }
    }
}

__global__ __launch_bounds__(256) void scan_final(float* __restrict__ out)
{
    int d = threadIdx.x;
    float cB = 0.f;
    for (int c0 = 0; c0 < NCH; c0 += 8) {
        float a[8], b[8];
        #pragma unroll
        for (int i = 0; i < 8; i++) {
            a[i] = g_cA[(c0+i)*D_ + d];
            b[i] = g_cB[(c0+i)*D_ + d];
        }
        #pragma unroll
        for (int i = 0; i < 8; i++)
            cB = fmaf(a[i], cB, b[i]);
    }
    out[d] = cB;
}

// ================= host launcher =================
extern "C" void kernel_launch(void* const* d_in, const int* in_sizes, int n_in,
                              void* d_out, int out_size)
{
    const float* story    = (const float*)d_in[0];
    const float* question = (const float*)d_in[1];
    const float* Wz_f     = (const float*)d_in[2];
    const float* bz_f     = (const float*)d_in[3];
    const float* Wh_f     = (const float*)d_in[4];
    const float* bh_f     = (const float*)d_in[5];
    const float* Wz_b     = (const float*)d_in[6];
    const float* bz_b     = (const float*)d_in[7];
    const float* Wh_b     = (const float*)d_in[8];
    const float* bh_b     = (const float*)d_in[9];
    float* out = (float*)d_out;

    cudaFuncSetAttribute(qrn_gemm,   cudaFuncAttributeMaxDynamicSharedMemorySize, SM_GEMM);
    cudaFuncSetAttribute(scan_apply, cudaFuncAttributeMaxDynamicSharedMemorySize, 131072);

    dim3 wb(32, 8), wg(8, 16, 2);
    prep_w<<<wg, wb>>>(Wz_f,            Wh_f,             0);
    prep_w<<<wg, wb>>>(Wz_b,            Wh_b,             1);
    prep_xu<<<T_*D_/512, 256>>>(story, question);
    qwh0<<<128, 128>>>(Wh_f, bh_f, Wh_b, bh_b, question);
    prep_w<<<wg, wb>>>(Wz_f + 65536,    Wh_f + 131072,    2);

    dim3 gg2(NCH, 1, 2);
    dim3 gg1(NCH, 1, 1);

    // ---- layer 0 (fwd+bwd merged) ----
    qrn_gemm<<<gg2, 512, SM_GEMM>>>(0, 1, 1, 1, bz_f, bz_b, nullptr, nullptr);
    prep_w<<<wg, wb>>>(Wz_b + 65536,    Wh_b + 131072,    3);
    prep_w<<<wg, wb>>>(Wz_f + 2*65536,  Wh_f + 2*131072,  4);
    scan_prefix<<<2, 256>>>();
    scan_apply<<<NCH, 256, 131072>>>(story);

    // ---- layer 1 ----
    qrn_gemm<<<gg2, 512, SM_GEMM>>>(2, 3, 0, 1, bz_f + 256, bz_b + 256, bh_f + 256, bh_b + 256);
    scan_prefix<<<2, 256>>>();
    scan_apply<<<NCH, 256, 131072>>>(story);

    // ---- layer 2 (forward only; composites only) ----
    qrn_gemm<<<gg1, 512, SM_GEMM>>>(4, 4, 0, 0, bz_f + 512, bz_b + 512, bh_f + 512, bh_b + 512);
    scan_final<<<1, 256>>>(out);
}

// round 9
// speedup vs baseline: 1.0502x; 1.0502x over previous
#include <cuda_runtime.h>
#include <cuda_fp16.h>
#include <cstdint>

#define T_ 65536
#define D_ 256
#define CHUNK 128
#define NCH (T_/CHUNK)   // 512

// ================= device scratch (no allocations allowed) =================
__device__ float g_af [T_*D_];
__device__ float g_bf [T_*D_];
__device__ float g_ab2[T_*D_];
__device__ float g_bb2[T_*D_];
__device__ float g_cA [2*NCH*D_];
__device__ float g_cB [2*NCH*D_];
__device__ float g_pref[2*NCH*D_];
__device__ float g_hbias[2][D_];        // layer0: bh + q0 @ Wh_bottom

__device__ __half g_xhi[T_*D_];                    // x hi (H-phase A operand)
__device__ __half g_uhi[T_*D_], g_ulo[T_*D_];      // u = x*q hi/lo (Z-phase)
__device__ __half g_qhi[T_*D_];                    // q hi (H-phase A operand)
__device__ __half g_wzT[5][D_*D_];      // [layerdir][n*256+k]
__device__ __half g_whT[5][D_*2*D_];    // [layerdir][n*512+k]

// ================= helpers =================
__device__ __forceinline__ uint32_t smem_u32(const void* p) {
    uint32_t a;
    asm("{ .reg .u64 t; cvta.to.shared.u64 t, %1; cvt.u32.u64 %0, t; }" : "=r"(a) : "l"(p));
    return a;
}
__device__ __forceinline__ void ldsm_x4(uint32_t (&r)[4], uint32_t addr) {
    asm volatile("ldmatrix.sync.aligned.m8n8.x4.shared.b16 {%0,%1,%2,%3}, [%4];"
                 : "=r"(r[0]), "=r"(r[1]), "=r"(r[2]), "=r"(r[3]) : "r"(addr));
}
__device__ __forceinline__ void mma16816(float (&d)[4], const uint32_t (&a)[4], const uint32_t* b) {
    asm volatile("mma.sync.aligned.m16n8k16.row.col.f32.f16.f16.f32 "
                 "{%0,%1,%2,%3}, {%4,%5,%6,%7}, {%8,%9}, {%0,%1,%2,%3};"
                 : "+f"(d[0]), "+f"(d[1]), "+f"(d[2]), "+f"(d[3])
                 : "r"(a[0]), "r"(a[1]), "r"(a[2]), "r"(a[3]), "r"(b[0]), "r"(b[1]));
}
__device__ __forceinline__ void cpa16(uint32_t dst, const void* src) {
    asm volatile("cp.async.cg.shared.global [%0], [%1], 16;" :: "r"(dst), "l"(src));
}
#define CP_COMMIT() asm volatile("cp.async.commit_group;" ::: "memory")
#define CP_WAIT1()  asm volatile("cp.async.wait_group 1;" ::: "memory")

__device__ __forceinline__ float sigf(float v)   { return 1.0f/(1.0f+__expf(-v)); }
__device__ __forceinline__ float tanhf_(float v) { return 1.0f - 2.0f/(__expf(2.0f*v)+1.0f); }
__device__ __forceinline__ void split2h(float v, __half& h, __half& l) {
    h = __float2half_rn(v);
    l = __float2half_rn(v - __half2float(h));
}

// ================= prep kernels =================
__global__ void prep_w(const float* __restrict__ Wz, const float* __restrict__ Wh, int ld)
{
    int mz = blockIdx.z;
    if (mz == 0 && blockIdx.y >= 8) return;
    const float* src = mz ? Wh : Wz;
    int Krows = mz ? 512 : 256;
    __half* dh = mz ? &g_whT[ld][0] : &g_wzT[ld][0];
    int k0 = blockIdx.y*32, n0 = blockIdx.x*32;
    int tx = threadIdx.x, ty = threadIdx.y;
    __shared__ float t[32][33];
    #pragma unroll
    for (int i = 0; i < 4; i++)
        t[ty + i*8][tx] = src[(size_t)(k0 + ty + i*8)*256 + n0 + tx];
    __syncthreads();
    #pragma unroll
    for (int i = 0; i < 4; i++)
        dh[(size_t)(n0 + ty + i*8)*Krows + k0 + tx] = __float2half_rn(t[tx][ty + i*8]);
}

// x hi + u0 = x*q hi/lo (single story read)
__global__ void prep_xu(const float* __restrict__ story, const float* __restrict__ q)
{
    size_t i = ((size_t)blockIdx.x*256 + threadIdx.x)*2;
    int d = (int)(i & (D_-1));
    float2 v = *(const float2*)(story + i);
    __half2 ph;
    ph.x = __float2half_rn(v.x); ph.y = __float2half_rn(v.y);
    *(__half2*)(g_xhi+i) = ph;
    float u0 = v.x * q[d], u1 = v.y * q[d+1];
    __half h0,l0,h1,l1;
    split2h(u0,h0,l0); split2h(u1,h1,l1);
    __half2 pu, pl; pu.x=h0; pu.y=h1; pl.x=l0; pl.y=l1;
    *(__half2*)(g_uhi+i) = pu; *(__half2*)(g_ulo+i) = pl;
}

// warp-per-(dir,n): hbias[dir][n] = bh[n] + sum_k q[k]*Wh[(256+k)*256+n]
__global__ void qwh0(const float* __restrict__ Whf, const float* __restrict__ bhf,
                     const float* __restrict__ Whb, const float* __restrict__ bhb,
                     const float* __restrict__ q)
{
    int gw = (blockIdx.x * blockDim.x + threadIdx.x) >> 5;
    int lane = threadIdx.x & 31;
    int dir = gw >> 8, n = gw & 255;
    const float* Wh = dir ? Whb : Whf;
    const float* bh = dir ? bhb : bhf;
    float acc = 0.f;
    #pragma unroll
    for (int kk = 0; kk < 8; kk++) {
        int k = kk*32 + lane;
        acc = fmaf(q[k], Wh[(size_t)(256+k)*256 + n], acc);
    }
    #pragma unroll
    for (int o = 16; o; o >>= 1) acc += __shfl_xor_sync(0xFFFFFFFFu, acc, o);
    if (lane == 0) g_hbias[dir][n] = bh[n] + acc;
}

// ================= fused GEMM (mma.sync fp16, N=128, 256 threads, 3-stage) =================
// Z-phase (steps 0..7): u hi+lo (2-pass).  H-phase (8..S-1): x/q hi only (1-pass).
// Stage (30720B): Ahi [0,10240) | Alo [10240,20480) | B [20480,30720)
#define STAGE_B 30720
#define NSTAGE 3
#define ZBUF_OFF (NSTAGE*STAGE_B)
#define SM_TOTAL (ZBUF_OFF + 67584)
#define TSTR 40

__device__ __forceinline__ void issue_stage(int s, uint32_t sb,
    int row0, int n0g, const __half* wz, const __half* wh, int tid)
{
    const __half *Ah, *B; int ka, kb, Kd;
    bool lo = (s < 8);
    if (s < 8)       { Ah=g_uhi; B=wz; ka=s*32;      kb=s*32;     Kd=256; }
    else if (s < 16) { Ah=g_xhi; B=wh; ka=(s-8)*32;  kb=(s-8)*32; Kd=512; }
    else             { Ah=g_qhi; B=wh; ka=(s-16)*32; kb=(s-8)*32; Kd=512; }
    #pragma unroll
    for (int i = 0; i < 6; i++) {
        int v = tid + i*256;          // 0..1535
        int t = v >> 9;               // 0=Ahi 1=Alo 2=B
        if (t == 1 && !lo) continue;
        int c = v & 511;
        int r = c >> 2, q = c & 3;
        const __half* sp = (t==0) ? Ah : (t==1) ? g_ulo : B;
        size_t so = (t < 2) ? ((size_t)(row0 + r)*256 + ka + q*8)
                            : ((size_t)(n0g + r)*Kd  + kb + q*8);
        cpa16(sb + (uint32_t)(t*10240 + r*80 + q*16), sp + so);
    }
}

__device__ __forceinline__ void mma_step(float (&acc)[2][8][4],
    uint32_t stg, int wm, int wn, int lane, bool use_lo)
{
    const uint32_t uA = stg, uB = stg + 20480;
    #pragma unroll
    for (int kk = 0; kk < 32; kk += 16) {
        uint32_t aH[2][4], aL[2][4], bb[8][2];
        #pragma unroll
        for (int mi = 0; mi < 2; mi++) {
            uint32_t roff = (uint32_t)(wm*32 + mi*16 + (lane & 15))*(TSTR*2)
                          + (uint32_t)(kk + ((lane >> 4) << 3))*2;
            ldsm_x4(aH[mi], uA + roff);
            if (use_lo) ldsm_x4(aL[mi], uA + 10240 + roff);
        }
        #pragma unroll
        for (int pi = 0; pi < 4; pi++) {
            uint32_t nrow = (uint32_t)(wn*64 + pi*16 + ((lane >> 4) << 3) + (lane & 7));
            uint32_t off = nrow*(TSTR*2) + (uint32_t)(kk + (((lane >> 3) & 1) << 3))*2;
            uint32_t t[4];
            ldsm_x4(t, uB + off);
            bb[pi*2][0]=t[0]; bb[pi*2][1]=t[1]; bb[pi*2+1][0]=t[2]; bb[pi*2+1][1]=t[3];
        }
        #pragma unroll
        for (int mi = 0; mi < 2; mi++)
            #pragma unroll
            for (int ni = 0; ni < 8; ni++) {
                mma16816(acc[mi][ni], aH[mi], bb[ni]);
                if (use_lo) mma16816(acc[mi][ni], aL[mi], bb[ni]);
            }
    }
}

__global__ __launch_bounds__(256, 1)
void qrn_gemm(int ld_f, int ld_b, int layer0, int store_ab,
              const float* __restrict__ bz_f_, const float* __restrict__ bz_b_,
              const float* __restrict__ bh_f_, const float* __restrict__ bh_b_)
{
    extern __shared__ __align__(16) char smem[];
    float* bbuf = (float*)smem;                      // aliases operand stages post-mainloop
    float* zbuf = (float*)(smem + ZBUF_OFF);
    __shared__ float s_bz[128], s_bh[128];
    __shared__ float s_pA[2][128], s_pB[2][128];

    const int tid = threadIdx.x, lane = tid & 31, warp = tid >> 5;
    const int wm = warp & 3, wn = warp >> 2;
    const int nh = blockIdx.x, ch = blockIdx.y;
    const int dir = blockIdx.z;
    const int ld = dir ? ld_b : ld_f;
    const int row0 = ch*CHUNK, n0g = nh*128;
    const uint32_t base = smem_u32(smem);

    if (tid < 128) {
        s_bz[tid] = (dir ? bz_b_ : bz_f_)[n0g + tid];
        s_bh[tid] = layer0 ? g_hbias[dir][n0g + tid]
                           : (dir ? bh_b_ : bh_f_)[n0g + tid];
    }

    const __half* wz = &g_wzT[ld][0];
    const __half* wh = &g_whT[ld][0];
    const int S = layer0 ? 16 : 24;

    float acc[2][8][4];
    #pragma unroll
    for (int mi = 0; mi < 2; mi++)
        #pragma unroll
        for (int ni = 0; ni < 8; ni++)
            #pragma unroll
            for (int j = 0; j < 4; j++) acc[mi][ni][j] = 0.f;

    issue_stage(0, base + 0*STAGE_B, row0, n0g, wz, wh, tid);
    CP_COMMIT();
    issue_stage(1, base + 1*STAGE_B, row0, n0g, wz, wh, tid);
    CP_COMMIT();

    for (int s = 0; s < S; s++) {
        CP_WAIT1();
        __syncthreads();
        if (s + 2 < S)
            issue_stage(s+2, base + ((s+2) % NSTAGE)*STAGE_B, row0, n0g, wz, wh, tid);
        CP_COMMIT();

        mma_step(acc, base + (s % NSTAGE)*STAGE_B, wm, wn, lane, s < 8);

        if (s == 7) {      // z epilogue -> zbuf, reset acc for H phase
            #pragma unroll
            for (int mi = 0; mi < 2; mi++) {
                int r0 = wm*32 + mi*16 + (lane >> 2);
                #pragma unroll
                for (int ni = 0; ni < 8; ni++) {
                    int cl = wn*64 + ni*8 + (lane & 3)*2;
                    zbuf[r0*132 + cl]     = sigf(acc[mi][ni][0] + s_bz[cl]);
                    zbuf[r0*132 + cl + 1] = sigf(acc[mi][ni][1] + s_bz[cl+1]);
                    zbuf[(r0+8)*132 + cl]     = sigf(acc[mi][ni][2] + s_bz[cl]);
                    zbuf[(r0+8)*132 + cl + 1] = sigf(acc[mi][ni][3] + s_bz[cl+1]);
                    #pragma unroll
                    for (int j = 0; j < 4; j++) acc[mi][ni][j] = 0.f;
                }
            }
        }
    }
    __syncthreads();   // all MMA done; operand smem reusable as bbuf

    // ---- final epilogue: a = 1-z (into zbuf), b = z*tanh(h+bh) -> bbuf ----
    #pragma unroll
    for (int mi = 0; mi < 2; mi++) {
        int r0 = wm*32 + mi*16 + (lane >> 2);
        #pragma unroll
        for (int ni = 0; ni < 8; ni++) {
            int cl = wn*64 + ni*8 + (lane & 3)*2;
            #pragma unroll
            for (int hrow = 0; hrow < 2; hrow++) {
                int r = r0 + hrow*8;
                float z0 = zbuf[r*132 + cl], z1 = zbuf[r*132 + cl + 1];
                float h0 = tanhf_(acc[mi][ni][hrow*2+0] + s_bh[cl]);
                float h1 = tanhf_(acc[mi][ni][hrow*2+1] + s_bh[cl+1]);
                bbuf[r*132 + cl]     = z0*h0;
                bbuf[r*132 + cl + 1] = z1*h1;
                zbuf[r*132 + cl]     = 1.0f - z0;
                zbuf[r*132 + cl + 1] = 1.0f - z1;
            }
        }
    }
    __syncthreads();

    // ---- global a,b stores ----
    if (store_ab) {
        float* outA = dir ? g_ab2 : g_af;
        float* outB = dir ? g_bb2 : g_bf;
        #pragma unroll
        for (int i = 0; i < 16; i++) {
            int r = (tid >> 5) + i*8;
            int c4 = (tid & 31)*4;
            float4 va = *(float4*)(zbuf + r*132 + c4);
            float4 vb = *(float4*)(bbuf + r*132 + c4);
            size_t o = (size_t)(row0 + r)*256 + n0g + c4;
            *(float4*)(outA + o) = va;
            *(float4*)(outB + o) = vb;
        }
    }

    // ---- per-chunk scan composites ----
    {
        int cc = tid & 127, seg = tid >> 7;
        float pa = 1.0f, pb = 0.0f;
        if (dir == 0) {
            for (int r = seg*64; r < seg*64 + 64; r++) {
                float a = zbuf[r*132 + cc], b = bbuf[r*132 + cc];
                pb = fmaf(a, pb, b); pa *= a;
            }
        } else {
            for (int r = seg*64 + 63; r >= seg*64; r--) {
                float a = zbuf[r*132 + cc], b = bbuf[r*132 + cc];
                pb = fmaf(a, pb, b); pa *= a;
            }
        }
        s_pA[seg][cc] = pa; s_pB[seg][cc] = pb;
    }
    __syncthreads();
    if (tid < 128) {
        float A, B;
        if (dir == 0) { A = s_pA[1][tid]*s_pA[0][tid]; B = fmaf(s_pA[1][tid], s_pB[0][tid], s_pB[1][tid]); }
        else          { A = s_pA[0][tid]*s_pA[1][tid]; B = fmaf(s_pA[0][tid], s_pB[1][tid], s_pB[0][tid]); }
        size_t o = ((size_t)dir*NCH + ch)*256 + n0g + tid;
        g_cA[o] = A; g_cB[o] = B;
    }
}

// ================= scan kernels =================
__global__ __launch_bounds__(256) void scan_prefix()
{
    int dir = blockIdx.x, d = threadIdx.x;
    float cB = 0.f;
    if (dir == 0) {
        for (int c0 = 0; c0 < NCH; c0 += 8) {
            float a[8], b[8];
            #pragma unroll
            for (int i = 0; i < 8; i++) {
                a[i] = g_cA[(c0+i)*D_ + d];
                b[i] = g_cB[(c0+i)*D_ + d];
            }
            #pragma unroll
            for (int i = 0; i < 8; i++) {
                g_pref[(c0+i)*D_ + d] = cB;
                cB = fmaf(a[i], cB, b[i]);
            }
        }
    } else {
        for (int c0 = NCH - 8; c0 >= 0; c0 -= 8) {
            float a[8], b[8];
            #pragma unroll
            for (int i = 0; i < 8; i++) {
                a[i] = g_cA[(NCH + c0+i)*D_ + d];
                b[i] = g_cB[(NCH + c0+i)*D_ + d];
            }
            #pragma unroll
            for (int i = 7; i >= 0; i--) {
                g_pref[(NCH + c0+i)*D_ + d] = cB;
                cB = fmaf(a[i], cB, b[i]);
            }
        }
    }
}

// fused fwd+bwd apply + next-layer operand prep (h_fwd staged in smem)
__global__ __launch_bounds__(256) void scan_apply(const float* __restrict__ story)
{
    extern __shared__ float hbuf[];   // 128 x 256
    int d = threadIdx.x, ch = blockIdx.x;

    float h = g_pref[ch*D_ + d];
    size_t base = (size_t)ch*CHUNK*D_ + d;
    for (int j0 = 0; j0 < CHUNK; j0 += 8) {
        float a[8], b[8];
        #pragma unroll
        for (int i = 0; i < 8; i++) {
            size_t o = base + (size_t)(j0+i)*D_;
            a[i] = g_af[o]; b[i] = g_bf[o];
        }
        #pragma unroll
        for (int i = 0; i < 8; i++) {
            h = fmaf(a[i], h, b[i]);
            hbuf[(j0+i)*256 + d] = h;
        }
    }
    __syncthreads();

    float h2 = g_pref[(NCH + ch)*D_ + d];
    size_t base2 = ((size_t)ch*CHUNK + CHUNK-1)*D_ + d;
    for (int j0 = 0; j0 < CHUNK; j0 += 8) {
        float a[8], b[8], x[8];
        #pragma unroll
        for (int i = 0; i < 8; i++) {
            size_t o = base2 - (size_t)(j0+i)*D_;
            a[i] = g_ab2[o]; b[i] = g_bb2[o]; x[i] = story[o];
        }
        #pragma unroll
        for (int i = 0; i < 8; i++) {
            size_t o = base2 - (size_t)(j0+i)*D_;
            h2 = fmaf(a[i], h2, b[i]);
            float q = hbuf[(CHUNK-1-(j0+i))*256 + d] + h2;
            float u = x[i] * q;
            __half uh, ul;
            split2h(u, uh, ul);
            g_qhi[o] = __float2half_rn(q);
            g_uhi[o] = uh; g_ulo[o] = ul;
        }
    }
}

__global__ __launch_bounds__(256) void scan_final(float* __restrict__ out)
{
    int d = threadIdx.x;
    float cB = 0.f;
    for (int c0 = 0; c0 < NCH; c0 += 8) {
        float a[8], b[8];
        #pragma unroll
        for (int i = 0; i < 8; i++) {
            a[i] = g_cA[(c0+i)*D_ + d];
            b[i] = g_cB[(c0+i)*D_ + d];
        }
        #pragma unroll
        for (int i = 0; i < 8; i++)
            cB = fmaf(a[i], cB, b[i]);
    }
    out[d] = cB;
}

// ================= host launcher =================
extern "C" void kernel_launch(void* const* d_in, const int* in_sizes, int n_in,
                              void* d_out, int out_size)
{
    const float* story    = (const float*)d_in[0];
    const float* question = (const float*)d_in[1];
    const float* Wz_f     = (const float*)d_in[2];
    const float* bz_f     = (const float*)d_in[3];
    const float* Wh_f     = (const float*)d_in[4];
    const float* bh_f     = (const float*)d_in[5];
    const float* Wz_b     = (const float*)d_in[6];
    const float* bz_b     = (const float*)d_in[7];
    const float* Wh_b     = (const float*)d_in[8];
    const float* bh_b     = (const float*)d_in[9];
    float* out = (float*)d_out;

    cudaFuncSetAttribute(qrn_gemm,   cudaFuncAttributeMaxDynamicSharedMemorySize, SM_TOTAL);
    cudaFuncSetAttribute(scan_apply, cudaFuncAttributeMaxDynamicSharedMemorySize, 131072);

    dim3 wb(32, 8), wg(8, 16, 2);
    prep_w<<<wg, wb>>>(Wz_f,            Wh_f,             0);
    prep_w<<<wg, wb>>>(Wz_b,            Wh_b,             1);
    prep_xu<<<T_*D_/512, 256>>>(story, question);
    qwh0<<<128, 128>>>(Wh_f, bh_f, Wh_b, bh_b, question);
    prep_w<<<wg, wb>>>(Wz_f + 65536,    Wh_f + 131072,    2);

    dim3 gg2(2, NCH, 2);   // (N-half, chunk, dir)
    dim3 gg1(2, NCH, 1);

    // ---- layer 0 (fwd+bwd merged) ----
    qrn_gemm<<<gg2, 256, SM_TOTAL>>>(0, 1, 1, 1, bz_f, bz_b, nullptr, nullptr);
    prep_w<<<wg, wb>>>(Wz_b + 65536,    Wh_b + 131072,    3);
    prep_w<<<wg, wb>>>(Wz_f + 2*65536,  Wh_f + 2*131072,  4);
    scan_prefix<<<2, 256>>>();
    scan_apply<<<NCH, 256, 131072>>>(story);

    // ---- layer 1 ----
    qrn_gemm<<<gg2, 256, SM_TOTAL>>>(2, 3, 0, 1, bz_f + 256, bz_b + 256, bh_f + 256, bh_b + 256);
    scan_prefix<<<2, 256>>>();
    scan_apply<<<NCH, 256, 131072>>>(story);

    // ---- layer 2 (forward only; composites only) ----
    qrn_gemm<<<gg1, 256, SM_TOTAL>>>(4, 4, 0, 0, bz_f + 512, bz_b + 512, bh_f + 512, bh_b + 512);
    scan_final<<<1, 256>>>(out);
}

// round 10
// speedup vs baseline: 1.0659x; 1.0150x over previous
#include <cuda_runtime.h>
#include <cuda_fp16.h>
#include <cstdint>

#define T_ 65536
#define D_ 256
#define CHUNK 128
#define NCH (T_/CHUNK)   // 512

// ================= device scratch (no allocations allowed) =================
__device__ float g_af [T_*D_];
__device__ float g_bf [T_*D_];
__device__ float g_ab2[T_*D_];
__device__ float g_bb2[T_*D_];
__device__ float g_cA [2*NCH*D_];
__device__ float g_cB [2*NCH*D_];
__device__ float g_pref[2*NCH*D_];
__device__ float g_hbias[2][D_];        // layer0: bh + q0 @ Wh_bottom

__device__ __half g_xhi[T_*D_];                    // x hi (H-phase A operand)
__device__ __half g_uhi[T_*D_], g_ulo[T_*D_];      // u = x*q hi/lo (Z-phase)
__device__ __half g_qhi[T_*D_];                    // q hi (H-phase A operand)
__device__ __half g_wzT[5][D_*D_];      // [layerdir][n*256+k]
__device__ __half g_whT[5][D_*2*D_];    // [layerdir][n*512+k]

// ================= helpers =================
__device__ __forceinline__ uint32_t smem_u32(const void* p) {
    uint32_t a;
    asm("{ .reg .u64 t; cvta.to.shared.u64 t, %1; cvt.u32.u64 %0, t; }" : "=r"(a) : "l"(p));
    return a;
}
__device__ __forceinline__ void ldsm_x4(uint32_t (&r)[4], uint32_t addr) {
    asm volatile("ldmatrix.sync.aligned.m8n8.x4.shared.b16 {%0,%1,%2,%3}, [%4];"
                 : "=r"(r[0]), "=r"(r[1]), "=r"(r[2]), "=r"(r[3]) : "r"(addr));
}
__device__ __forceinline__ void mma16816(float (&d)[4], const uint32_t (&a)[4], const uint32_t* b) {
    asm volatile("mma.sync.aligned.m16n8k16.row.col.f32.f16.f16.f32 "
                 "{%0,%1,%2,%3}, {%4,%5,%6,%7}, {%8,%9}, {%0,%1,%2,%3};"
                 : "+f"(d[0]), "+f"(d[1]), "+f"(d[2]), "+f"(d[3])
                 : "r"(a[0]), "r"(a[1]), "r"(a[2]), "r"(a[3]), "r"(b[0]), "r"(b[1]));
}
__device__ __forceinline__ void cpa16(uint32_t dst, const void* src) {
    asm volatile("cp.async.cg.shared.global [%0], [%1], 16;" :: "r"(dst), "l"(src));
}
#define CP_COMMIT() asm volatile("cp.async.commit_group;" ::: "memory")
#define CP_WAIT3()  asm volatile("cp.async.wait_group 3;" ::: "memory")

__device__ __forceinline__ float sigf(float v)   { return 1.0f/(1.0f+__expf(-v)); }
__device__ __forceinline__ float tanhf_(float v) { return 1.0f - 2.0f/(__expf(2.0f*v)+1.0f); }
__device__ __forceinline__ void split2h(float v, __half& h, __half& l) {
    h = __float2half_rn(v);
    l = __float2half_rn(v - __half2float(h));
}

// ================= prep kernels =================
__global__ void prep_w(const float* __restrict__ Wz, const float* __restrict__ Wh, int ld)
{
    int mz = blockIdx.z;
    if (mz == 0 && blockIdx.y >= 8) return;
    const float* src = mz ? Wh : Wz;
    int Krows = mz ? 512 : 256;
    __half* dh = mz ? &g_whT[ld][0] : &g_wzT[ld][0];
    int k0 = blockIdx.y*32, n0 = blockIdx.x*32;
    int tx = threadIdx.x, ty = threadIdx.y;
    __shared__ float t[32][33];
    #pragma unroll
    for (int i = 0; i < 4; i++)
        t[ty + i*8][tx] = src[(size_t)(k0 + ty + i*8)*256 + n0 + tx];
    __syncthreads();
    #pragma unroll
    for (int i = 0; i < 4; i++)
        dh[(size_t)(n0 + ty + i*8)*Krows + k0 + tx] = __float2half_rn(t[tx][ty + i*8]);
}

// x hi + u0 = x*q hi/lo (single story read)
__global__ void prep_xu(const float* __restrict__ story, const float* __restrict__ q)
{
    size_t i = ((size_t)blockIdx.x*256 + threadIdx.x)*2;
    int d = (int)(i & (D_-1));
    float2 v = *(const float2*)(story + i);
    __half2 ph;
    ph.x = __float2half_rn(v.x); ph.y = __float2half_rn(v.y);
    *(__half2*)(g_xhi+i) = ph;
    float u0 = v.x * q[d], u1 = v.y * q[d+1];
    __half h0,l0,h1,l1;
    split2h(u0,h0,l0); split2h(u1,h1,l1);
    __half2 pu, pl; pu.x=h0; pu.y=h1; pl.x=l0; pl.y=l1;
    *(__half2*)(g_uhi+i) = pu; *(__half2*)(g_ulo+i) = pl;
}

// warp-per-(dir,n): hbias[dir][n] = bh[n] + sum_k q[k]*Wh[(256+k)*256+n]
__global__ void qwh0(const float* __restrict__ Whf, const float* __restrict__ bhf,
                     const float* __restrict__ Whb, const float* __restrict__ bhb,
                     const float* __restrict__ q)
{
    int gw = (blockIdx.x * blockDim.x + threadIdx.x) >> 5;
    int lane = threadIdx.x & 31;
    int dir = gw >> 8, n = gw & 255;
    const float* Wh = dir ? Whb : Whf;
    const float* bh = dir ? bhb : bhf;
    float acc = 0.f;
    #pragma unroll
    for (int kk = 0; kk < 8; kk++) {
        int k = kk*32 + lane;
        acc = fmaf(q[k], Wh[(size_t)(256+k)*256 + n], acc);
    }
    #pragma unroll
    for (int o = 16; o; o >>= 1) acc += __shfl_xor_sync(0xFFFFFFFFu, acc, o);
    if (lane == 0) g_hbias[dir][n] = bh[n] + acc;
}

// ================= fused GEMM (mma.sync fp16, uniform stages, 5-deep ring) =================
// Z = [uhi; ulo] @ [Wz; Wz] (K-concat; math identical to hi/lo 2-pass).
// Stage (20480B): A [0,10240) | B [10240,20480), rows padded to 40 halves.
// Steps: 0-7 uhi@Wz, 8-15 ulo@Wz, 16-23 x@Wh(top), 24-31 q@Wh(bottom).
#define STAGE_B 20480
#define NSTAGE 5
#define ZBUF_OFF (NSTAGE*STAGE_B)                 // 102400
#define SM_TOTAL (ZBUF_OFF + 67584)               // 169984
#define TSTR 40

__device__ __forceinline__ void issue_stage(int s, uint32_t sb,
    int row0, int n0g, const __half* wz, const __half* wh, int tid)
{
    const __half *A, *B; int ka, kb, Kd;
    if (s < 8)       { A=g_uhi; B=wz; ka=s*32;       kb=s*32;       Kd=256; }
    else if (s < 16) { A=g_ulo; B=wz; ka=(s-8)*32;   kb=(s-8)*32;   Kd=256; }
    else if (s < 24) { A=g_xhi; B=wh; ka=(s-16)*32;  kb=(s-16)*32;  Kd=512; }
    else             { A=g_qhi; B=wh; ka=(s-24)*32;  kb=(s-16)*32;  Kd=512; }
    #pragma unroll
    for (int i = 0; i < 4; i++) {
        int v = tid + i*256;          // 0..1023
        int t = v >> 9;               // 0=A 1=B
        int c = v & 511;
        int r = c >> 2, q = c & 3;
        const __half* sp = t ? B : A;
        size_t so = t ? ((size_t)(n0g + r)*Kd  + kb + q*8)
                      : ((size_t)(row0 + r)*256 + ka + q*8);
        cpa16(sb + (uint32_t)(t*10240 + r*80 + q*16), sp + so);
    }
}

__device__ __forceinline__ void mma_step(float (&acc)[2][8][4],
    uint32_t stg, int wm, int wn, int lane)
{
    const uint32_t uA = stg, uB = stg + 10240;
    #pragma unroll
    for (int kk = 0; kk < 32; kk += 16) {
        uint32_t aH[2][4], bb[8][2];
        #pragma unroll
        for (int mi = 0; mi < 2; mi++) {
            uint32_t roff = (uint32_t)(wm*32 + mi*16 + (lane & 15))*(TSTR*2)
                          + (uint32_t)(kk + ((lane >> 4) << 3))*2;
            ldsm_x4(aH[mi], uA + roff);
        }
        #pragma unroll
        for (int pi = 0; pi < 4; pi++) {
            uint32_t nrow = (uint32_t)(wn*64 + pi*16 + ((lane >> 4) << 3) + (lane & 7));
            uint32_t off = nrow*(TSTR*2) + (uint32_t)(kk + (((lane >> 3) & 1) << 3))*2;
            uint32_t t[4];
            ldsm_x4(t, uB + off);
            bb[pi*2][0]=t[0]; bb[pi*2][1]=t[1]; bb[pi*2+1][0]=t[2]; bb[pi*2+1][1]=t[3];
        }
        #pragma unroll
        for (int mi = 0; mi < 2; mi++)
            #pragma unroll
            for (int ni = 0; ni < 8; ni++)
                mma16816(acc[mi][ni], aH[mi], bb[ni]);
    }
}

__global__ __launch_bounds__(256, 1)
void qrn_gemm(int ld_f, int ld_b, int layer0, int store_ab,
              const float* __restrict__ bz_f_, const float* __restrict__ bz_b_,
              const float* __restrict__ bh_f_, const float* __restrict__ bh_b_)
{
    extern __shared__ __align__(16) char smem[];
    float* bbuf = (float*)smem;                      // aliases operand stages post-mainloop
    float* zbuf = (float*)(smem + ZBUF_OFF);
    __shared__ float s_bz[128], s_bh[128];
    __shared__ float s_pA[2][128], s_pB[2][128];

    const int tid = threadIdx.x, lane = tid & 31, warp = tid >> 5;
    const int wm = warp & 3, wn = warp >> 2;
    const int nh = blockIdx.x, ch = blockIdx.y;
    const int dir = blockIdx.z;
    const int ld = dir ? ld_b : ld_f;
    const int row0 = ch*CHUNK, n0g = nh*128;
    const uint32_t base = smem_u32(smem);

    if (tid < 128) {
        s_bz[tid] = (dir ? bz_b_ : bz_f_)[n0g + tid];
        s_bh[tid] = layer0 ? g_hbias[dir][n0g + tid]
                           : (dir ? bh_b_ : bh_f_)[n0g + tid];
    }

    const __half* wz = &g_wzT[ld][0];
    const __half* wh = &g_whT[ld][0];
    const int S = layer0 ? 24 : 32;     // 16 Z-steps + 8/16 H-steps

    float acc[2][8][4];
    #pragma unroll
    for (int mi = 0; mi < 2; mi++)
        #pragma unroll
        for (int ni = 0; ni < 8; ni++)
            #pragma unroll
            for (int j = 0; j < 4; j++) acc[mi][ni][j] = 0.f;

    #pragma unroll
    for (int p = 0; p < 4; p++) {
        issue_stage(p, base + p*STAGE_B, row0, n0g, wz, wh, tid);
        CP_COMMIT();
    }

    for (int s = 0; s < S; s++) {
        CP_WAIT3();        // stage s resident (uniform: every iter commits exactly 1 group)
        __syncthreads();
        if (s + 4 < S)
            issue_stage(s+4, base + ((s+4) % NSTAGE)*STAGE_B, row0, n0g, wz, wh, tid);
        CP_COMMIT();

        mma_step(acc, base + (s % NSTAGE)*STAGE_B, wm, wn, lane);

        if (s == 15) {     // z epilogue -> zbuf, reset acc for H phase
            #pragma unroll
            for (int mi = 0; mi < 2; mi++) {
                int r0 = wm*32 + mi*16 + (lane >> 2);
                #pragma unroll
                for (int ni = 0; ni < 8; ni++) {
                    int cl = wn*64 + ni*8 + (lane & 3)*2;
                    zbuf[r0*132 + cl]     = sigf(acc[mi][ni][0] + s_bz[cl]);
                    zbuf[r0*132 + cl + 1] = sigf(acc[mi][ni][1] + s_bz[cl+1]);
                    zbuf[(r0+8)*132 + cl]     = sigf(acc[mi][ni][2] + s_bz[cl]);
                    zbuf[(r0+8)*132 + cl + 1] = sigf(acc[mi][ni][3] + s_bz[cl+1]);
                    #pragma unroll
                    for (int j = 0; j < 4; j++) acc[mi][ni][j] = 0.f;
                }
            }
        }
    }
    __syncthreads();   // all MMA done; operand smem reusable as bbuf

    // ---- final epilogue: a = 1-z (into zbuf), b = z*tanh(h+bh) -> bbuf ----
    #pragma unroll
    for (int mi = 0; mi < 2; mi++) {
        int r0 = wm*32 + mi*16 + (lane >> 2);
        #pragma unroll
        for (int ni = 0; ni < 8; ni++) {
            int cl = wn*64 + ni*8 + (lane & 3)*2;
            #pragma unroll
            for (int hrow = 0; hrow < 2; hrow++) {
                int r = r0 + hrow*8;
                float z0 = zbuf[r*132 + cl], z1 = zbuf[r*132 + cl + 1];
                float h0 = tanhf_(acc[mi][ni][hrow*2+0] + s_bh[cl]);
                float h1 = tanhf_(acc[mi][ni][hrow*2+1] + s_bh[cl+1]);
                bbuf[r*132 + cl]     = z0*h0;
                bbuf[r*132 + cl + 1] = z1*h1;
                zbuf[r*132 + cl]     = 1.0f - z0;
                zbuf[r*132 + cl + 1] = 1.0f - z1;
            }
        }
    }
    __syncthreads();

    // ---- global a,b stores ----
    if (store_ab) {
        float* outA = dir ? g_ab2 : g_af;
        float* outB = dir ? g_bb2 : g_bf;
        #pragma unroll
        for (int i = 0; i < 16; i++) {
            int r = (tid >> 5) + i*8;
            int c4 = (tid & 31)*4;
            float4 va = *(float4*)(zbuf + r*132 + c4);
            float4 vb = *(float4*)(bbuf + r*132 + c4);
            size_t o = (size_t)(row0 + r)*256 + n0g + c4;
            *(float4*)(outA + o) = va;
            *(float4*)(outB + o) = vb;
        }
    }

    // ---- per-chunk scan composites ----
    {
        int cc = tid & 127, seg = tid >> 7;
        float pa = 1.0f, pb = 0.0f;
        if (dir == 0) {
            for (int r = seg*64; r < seg*64 + 64; r++) {
                float a = zbuf[r*132 + cc], b = bbuf[r*132 + cc];
                pb = fmaf(a, pb, b); pa *= a;
            }
        } else {
            for (int r = seg*64 + 63; r >= seg*64; r--) {
                float a = zbuf[r*132 + cc], b = bbuf[r*132 + cc];
                pb = fmaf(a, pb, b); pa *= a;
            }
        }
        s_pA[seg][cc] = pa; s_pB[seg][cc] = pb;
    }
    __syncthreads();
    if (tid < 128) {
        float A, B;
        if (dir == 0) { A = s_pA[1][tid]*s_pA[0][tid]; B = fmaf(s_pA[1][tid], s_pB[0][tid], s_pB[1][tid]); }
        else          { A = s_pA[0][tid]*s_pA[1][tid]; B = fmaf(s_pA[0][tid], s_pB[1][tid], s_pB[0][tid]); }
        size_t o = ((size_t)dir*NCH + ch)*256 + n0g + tid;
        g_cA[o] = A; g_cB[o] = B;
    }
}

// ================= scan kernels =================
__global__ __launch_bounds__(256) void scan_prefix()
{
    int dir = blockIdx.x, d = threadIdx.x;
    float cB = 0.f;
    if (dir == 0) {
        for (int c0 = 0; c0 < NCH; c0 += 8) {
            float a[8], b[8];
            #pragma unroll
            for (int i = 0; i < 8; i++) {
                a[i] = g_cA[(c0+i)*D_ + d];
                b[i] = g_cB[(c0+i)*D_ + d];
            }
            #pragma unroll
            for (int i = 0; i < 8; i++) {
                g_pref[(c0+i)*D_ + d] = cB;
                cB = fmaf(a[i], cB, b[i]);
            }
        }
    } else {
        for (int c0 = NCH - 8; c0 >= 0; c0 -= 8) {
            float a[8], b[8];
            #pragma unroll
            for (int i = 0; i < 8; i++) {
                a[i] = g_cA[(NCH + c0+i)*D_ + d];
                b[i] = g_cB[(NCH + c0+i)*D_ + d];
            }
            #pragma unroll
            for (int i = 7; i >= 0; i--) {
                g_pref[(NCH + c0+i)*D_ + d] = cB;
                cB = fmaf(a[i], cB, b[i]);
            }
        }
    }
}

// fused fwd+bwd apply + next-layer operand prep (h_fwd staged in smem)
__global__ __launch_bounds__(256) void scan_apply(const float* __restrict__ story)
{
    extern __shared__ float hbuf[];   // 128 x 256
    int d = threadIdx.x, ch = blockIdx.x;

    float h = g_pref[ch*D_ + d];
    size_t base = (size_t)ch*CHUNK*D_ + d;
    for (int j0 = 0; j0 < CHUNK; j0 += 8) {
        float a[8], b[8];
        #pragma unroll
        for (int i = 0; i < 8; i++) {
            size_t o = base + (size_t)(j0+i)*D_;
            a[i] = g_af[o]; b[i] = g_bf[o];
        }
        #pragma unroll
        for (int i = 0; i < 8; i++) {
            h = fmaf(a[i], h, b[i]);
            hbuf[(j0+i)*256 + d] = h;
        }
    }
    __syncthreads();

    float h2 = g_pref[(NCH + ch)*D_ + d];
    size_t base2 = ((size_t)ch*CHUNK + CHUNK-1)*D_ + d;
    for (int j0 = 0; j0 < CHUNK; j0 += 8) {
        float a[8], b[8], x[8];
        #pragma unroll
        for (int i = 0; i < 8; i++) {
            size_t o = base2 - (size_t)(j0+i)*D_;
            a[i] = g_ab2[o]; b[i] = g_bb2[o]; x[i] = story[o];
        }
        #pragma unroll
        for (int i = 0; i < 8; i++) {
            size_t o = base2 - (size_t)(j0+i)*D_;
            h2 = fmaf(a[i], h2, b[i]);
            float q = hbuf[(CHUNK-1-(j0+i))*256 + d] + h2;
            float u = x[i] * q;
            __half uh, ul;
            split2h(u, uh, ul);
            g_qhi[o] = __float2half_rn(q);
            g_uhi[o] = uh; g_ulo[o] = ul;
        }
    }
}

__global__ __launch_bounds__(256) void scan_final(float* __restrict__ out)
{
    int d = threadIdx.x;
    float cB = 0.f;
    for (int c0 = 0; c0 < NCH; c0 += 8) {
        float a[8], b[8];
        #pragma unroll
        for (int i = 0; i < 8; i++) {
            a[i] = g_cA[(c0+i)*D_ + d];
            b[i] = g_cB[(c0+i)*D_ + d];
        }
        #pragma unroll
        for (int i = 0; i < 8; i++)
            cB = fmaf(a[i], cB, b[i]);
    }
    out[d] = cB;
}

// ================= host launcher =================
extern "C" void kernel_launch(void* const* d_in, const int* in_sizes, int n_in,
                              void* d_out, int out_size)
{
    const float* story    = (const float*)d_in[0];
    const float* question = (const float*)d_in[1];
    const float* Wz_f     = (const float*)d_in[2];
    const float* bz_f     = (const float*)d_in[3];
    const float* Wh_f     = (const float*)d_in[4];
    const float* bh_f     = (const float*)d_in[5];
    const float* Wz_b     = (const float*)d_in[6];
    const float* bz_b     = (const float*)d_in[7];
    const float* Wh_b     = (const float*)d_in[8];
    const float* bh_b     = (const float*)d_in[9];
    float* out = (float*)d_out;

    cudaFuncSetAttribute(qrn_gemm,   cudaFuncAttributeMaxDynamicSharedMemorySize, SM_TOTAL);
    cudaFuncSetAttribute(scan_apply, cudaFuncAttributeMaxDynamicSharedMemorySize, 131072);

    dim3 wb(32, 8), wg(8, 16, 2);
    prep_w<<<wg, wb>>>(Wz_f,            Wh_f,             0);
    prep_w<<<wg, wb>>>(Wz_b,            Wh_b,             1);
    prep_xu<<<T_*D_/512, 256>>>(story, question);
    qwh0<<<128, 128>>>(Wh_f, bh_f, Wh_b, bh_b, question);
    prep_w<<<wg, wb>>>(Wz_f + 65536,    Wh_f + 131072,    2);

    dim3 gg2(2, NCH, 2);   // (N-half, chunk, dir)
    dim3 gg1(2, NCH, 1);

    // ---- layer 0 (fwd+bwd merged) ----
    qrn_gemm<<<gg2, 256, SM_TOTAL>>>(0, 1, 1, 1, bz_f, bz_b, nullptr, nullptr);
    prep_w<<<wg, wb>>>(Wz_b + 65536,    Wh_b + 131072,    3);
    prep_w<<<wg, wb>>>(Wz_f + 2*65536,  Wh_f + 2*131072,  4);
    scan_prefix<<<2, 256>>>();
    scan_apply<<<NCH, 256, 131072>>>(story);

    // ---- layer 1 ----
    qrn_gemm<<<gg2, 256, SM_TOTAL>>>(2, 3, 0, 1, bz_f + 256, bz_b + 256, bh_f + 256, bh_b + 256);
    scan_prefix<<<2, 256>>>();
    scan_apply<<<NCH, 256, 131072>>>(story);

    // ---- layer 2 (forward only; composites only) ----
    qrn_gemm<<<gg1, 256, SM_TOTAL>>>(4, 4, 0, 0, bz_f + 512, bz_b + 512, bh_f + 512, bh_b + 512);
    scan_final<<<1, 256>>>(out);
}

// round 11
// speedup vs baseline: 1.0717x; 1.0054x over previous
#include <cuda_runtime.h>
#include <cuda_fp16.h>
#include <cstdint>

#define T_ 65536
#define D_ 256
#define CHUNK 128
#define NCH (T_/CHUNK)   // 512

// ================= device scratch (no allocations allowed) =================
__device__ float g_af [T_*D_];
__device__ float g_bf [T_*D_];
__device__ float g_ab2[T_*D_];
__device__ float g_bb2[T_*D_];
__device__ float g_cA [2*NCH*D_];
__device__ float g_cB [2*NCH*D_];
__device__ float g_pref[2*NCH*D_];
__device__ float g_hbias[2][D_];        // layer0: bh + q0 @ Wh_bottom

__device__ __half g_xhi[T_*D_];                    // x hi (H-phase A operand)
__device__ __half g_uhi[T_*D_], g_ulo[T_*D_];      // u = x*q hi/lo (Z-phase)
__device__ __half g_qhi[T_*D_];                    // q hi (H-phase A operand)
__device__ __half g_wzT[5][D_*D_];      // [layerdir][n*256+k]
__device__ __half g_whT[5][D_*2*D_];    // [layerdir][n*512+k]

// ================= helpers =================
__device__ __forceinline__ uint32_t smem_u32(const void* p) {
    uint32_t a;
    asm("{ .reg .u64 t; cvta.to.shared.u64 t, %1; cvt.u32.u64 %0, t; }" : "=r"(a) : "l"(p));
    return a;
}
__device__ __forceinline__ void ldsm_x4(uint32_t (&r)[4], uint32_t addr) {
    asm volatile("ldmatrix.sync.aligned.m8n8.x4.shared.b16 {%0,%1,%2,%3}, [%4];"
                 : "=r"(r[0]), "=r"(r[1]), "=r"(r[2]), "=r"(r[3]) : "r"(addr));
}
__device__ __forceinline__ void mma16816(float (&d)[4], const uint32_t (&a)[4], const uint32_t* b) {
    asm volatile("mma.sync.aligned.m16n8k16.row.col.f32.f16.f16.f32 "
                 "{%0,%1,%2,%3}, {%4,%5,%6,%7}, {%8,%9}, {%0,%1,%2,%3};"
                 : "+f"(d[0]), "+f"(d[1]), "+f"(d[2]), "+f"(d[3])
                 : "r"(a[0]), "r"(a[1]), "r"(a[2]), "r"(a[3]), "r"(b[0]), "r"(b[1]));
}
__device__ __forceinline__ void cpa16(uint32_t dst, const void* src) {
    asm volatile("cp.async.cg.shared.global [%0], [%1], 16;" :: "r"(dst), "l"(src));
}
#define CP_COMMIT() asm volatile("cp.async.commit_group;" ::: "memory")
#define CP_WAIT4()  asm volatile("cp.async.wait_group 4;" ::: "memory")

__device__ __forceinline__ float sigf(float v)   { return 1.0f/(1.0f+__expf(-v)); }
__device__ __forceinline__ float tanhf_(float v) { return 1.0f - 2.0f/(__expf(2.0f*v)+1.0f); }
__device__ __forceinline__ void split2h(float v, __half& h, __half& l) {
    h = __float2half_rn(v);
    l = __float2half_rn(v - __half2float(h));
}

// ================= prep kernels =================
// ALL weight transposes in one launch: blockIdx.z encodes (ld, mz): z = ld*2 + mz
__global__ void prep_w(const float* __restrict__ Wz0, const float* __restrict__ Wh0,
                       const float* __restrict__ Wz1, const float* __restrict__ Wh1,
                       const float* __restrict__ Wz2, const float* __restrict__ Wh2,
                       const float* __restrict__ Wz3, const float* __restrict__ Wh3,
                       const float* __restrict__ Wz4, const float* __restrict__ Wh4)
{
    int ld = blockIdx.z >> 1, mz = blockIdx.z & 1;
    if (mz == 0 && blockIdx.y >= 8) return;
    const float* srcs[10] = {Wz0, Wh0, Wz1, Wh1, Wz2, Wh2, Wz3, Wh3, Wz4, Wh4};
    const float* src = srcs[blockIdx.z];
    int Krows = mz ? 512 : 256;
    __half* dh = mz ? &g_whT[ld][0] : &g_wzT[ld][0];
    int k0 = blockIdx.y*32, n0 = blockIdx.x*32;
    int tx = threadIdx.x, ty = threadIdx.y;
    __shared__ float t[32][33];
    #pragma unroll
    for (int i = 0; i < 4; i++)
        t[ty + i*8][tx] = src[(size_t)(k0 + ty + i*8)*256 + n0 + tx];
    __syncthreads();
    #pragma unroll
    for (int i = 0; i < 4; i++)
        dh[(size_t)(n0 + ty + i*8)*Krows + k0 + tx] = __float2half_rn(t[tx][ty + i*8]);
}

// x hi + u0 = x*q hi/lo (single story read)
__global__ void prep_xu(const float* __restrict__ story, const float* __restrict__ q)
{
    size_t i = ((size_t)blockIdx.x*256 + threadIdx.x)*2;
    int d = (int)(i & (D_-1));
    float2 v = *(const float2*)(story + i);
    __half2 ph;
    ph.x = __float2half_rn(v.x); ph.y = __float2half_rn(v.y);
    *(__half2*)(g_xhi+i) = ph;
    float u0 = v.x * q[d], u1 = v.y * q[d+1];
    __half h0,l0,h1,l1;
    split2h(u0,h0,l0); split2h(u1,h1,l1);
    __half2 pu, pl; pu.x=h0; pu.y=h1; pl.x=l0; pl.y=l1;
    *(__half2*)(g_uhi+i) = pu; *(__half2*)(g_ulo+i) = pl;
}

// warp-per-(dir,n): hbias[dir][n] = bh[n] + sum_k q[k]*Wh[(256+k)*256+n]
__global__ void qwh0(const float* __restrict__ Whf, const float* __restrict__ bhf,
                     const float* __restrict__ Whb, const float* __restrict__ bhb,
                     const float* __restrict__ q)
{
    int gw = (blockIdx.x * blockDim.x + threadIdx.x) >> 5;
    int lane = threadIdx.x & 31;
    int dir = gw >> 8, n = gw & 255;
    const float* Wh = dir ? Whb : Whf;
    const float* bh = dir ? bhb : bhf;
    float acc = 0.f;
    #pragma unroll
    for (int kk = 0; kk < 8; kk++) {
        int k = kk*32 + lane;
        acc = fmaf(q[k], Wh[(size_t)(256+k)*256 + n], acc);
    }
    #pragma unroll
    for (int o = 16; o; o >>= 1) acc += __shfl_xor_sync(0xFFFFFFFFu, acc, o);
    if (lane == 0) g_hbias[dir][n] = bh[n] + acc;
}

// ================= fused GEMM (mma.sync fp16, uniform stages, 6-deep ring) =================
// Z = [uhi; ulo] @ [Wz; Wz] (K-concat).  Stage 20480B: A | B, rows padded to 40 halves.
// Steps: 0-7 uhi@Wz, 8-15 ulo@Wz, 16-23 x@Wh(top), 24-31 q@Wh(bottom).
#define STAGE_B 20480
#define NSTAGE 6
#define ZBUF_OFF (NSTAGE*STAGE_B)                 // 122880
#define SM_TOTAL (ZBUF_OFF + 67584)               // 190464
#define TSTR 40

__device__ __forceinline__ void issue_stage(int s, uint32_t sb,
    int row0, int n0g, const __half* wz, const __half* wh, int tid)
{
    const __half *A, *B; int ka, kb, Kd;
    if (s < 8)       { A=g_uhi; B=wz; ka=s*32;       kb=s*32;       Kd=256; }
    else if (s < 16) { A=g_ulo; B=wz; ka=(s-8)*32;   kb=(s-8)*32;   Kd=256; }
    else if (s < 24) { A=g_xhi; B=wh; ka=(s-16)*32;  kb=(s-16)*32;  Kd=512; }
    else             { A=g_qhi; B=wh; ka=(s-24)*32;  kb=(s-16)*32;  Kd=512; }
    #pragma unroll
    for (int i = 0; i < 4; i++) {
        int v = tid + i*256;          // 0..1023
        int t = v >> 9;               // 0=A 1=B
        int c = v & 511;
        int r = c >> 2, q = c & 3;
        const __half* sp = t ? B : A;
        size_t so = t ? ((size_t)(n0g + r)*Kd  + kb + q*8)
                      : ((size_t)(row0 + r)*256 + ka + q*8);
        cpa16(sb + (uint32_t)(t*10240 + r*80 + q*16), sp + so);
    }
}

__device__ __forceinline__ void mma_step(float (&acc)[2][8][4],
    uint32_t stg, int wm, int wn, int lane)
{
    const uint32_t uA = stg, uB = stg + 10240;
    #pragma unroll
    for (int kk = 0; kk < 32; kk += 16) {
        uint32_t aH[2][4], bb[8][2];
        #pragma unroll
        for (int mi = 0; mi < 2; mi++) {
            uint32_t roff = (uint32_t)(wm*32 + mi*16 + (lane & 15))*(TSTR*2)
                          + (uint32_t)(kk + ((lane >> 4) << 3))*2;
            ldsm_x4(aH[mi], uA + roff);
        }
        #pragma unroll
        for (int pi = 0; pi < 4; pi++) {
            uint32_t nrow = (uint32_t)(wn*64 + pi*16 + ((lane >> 4) << 3) + (lane & 7));
            uint32_t off = nrow*(TSTR*2) + (uint32_t)(kk + (((lane >> 3) & 1) << 3))*2;
            uint32_t t[4];
            ldsm_x4(t, uB + off);
            bb[pi*2][0]=t[0]; bb[pi*2][1]=t[1]; bb[pi*2+1][0]=t[2]; bb[pi*2+1][1]=t[3];
        }
        #pragma unroll
        for (int mi = 0; mi < 2; mi++)
            #pragma unroll
            for (int ni = 0; ni < 8; ni++)
                mma16816(acc[mi][ni], aH[mi], bb[ni]);
    }
}

__global__ __launch_bounds__(256, 1)
void qrn_gemm(int ld_f, int ld_b, int layer0, int store_ab,
              const float* __restrict__ bz_f_, const float* __restrict__ bz_b_,
              const float* __restrict__ bh_f_, const float* __restrict__ bh_b_)
{
    extern __shared__ __align__(16) char smem[];
    float* bbuf = (float*)smem;                      // aliases operand stages post-mainloop
    float* zbuf = (float*)(smem + ZBUF_OFF);
    __shared__ float s_bz[128], s_bh[128];
    __shared__ float s_pA[2][128], s_pB[2][128];

    const int tid = threadIdx.x, lane = tid & 31, warp = tid >> 5;
    const int wm = warp & 3, wn = warp >> 2;
    const int nh = blockIdx.x, ch = blockIdx.y;
    const int dir = blockIdx.z;
    const int ld = dir ? ld_b : ld_f;
    const int row0 = ch*CHUNK, n0g = nh*128;
    const uint32_t base = smem_u32(smem);

    if (tid < 128) {
        s_bz[tid] = (dir ? bz_b_ : bz_f_)[n0g + tid];
        s_bh[tid] = layer0 ? g_hbias[dir][n0g + tid]
                           : (dir ? bh_b_ : bh_f_)[n0g + tid];
    }

    const __half* wz = &g_wzT[ld][0];
    const __half* wh = &g_whT[ld][0];
    const int S = layer0 ? 24 : 32;     // 16 Z-steps + 8/16 H-steps

    float acc[2][8][4];
    #pragma unroll
    for (int mi = 0; mi < 2; mi++)
        #pragma unroll
        for (int ni = 0; ni < 8; ni++)
            #pragma unroll
            for (int j = 0; j < 4; j++) acc[mi][ni][j] = 0.f;

    #pragma unroll
    for (int p = 0; p < 5; p++) {
        issue_stage(p, base + p*STAGE_B, row0, n0g, wz, wh, tid);
        CP_COMMIT();
    }

    for (int s = 0; s < S; s++) {
        CP_WAIT4();        // stage s resident (uniform: every iter commits exactly 1 group)
        __syncthreads();
        if (s + 5 < S)
            issue_stage(s+5, base + ((s+5) % NSTAGE)*STAGE_B, row0, n0g, wz, wh, tid);
        CP_COMMIT();

        mma_step(acc, base + (s % NSTAGE)*STAGE_B, wm, wn, lane);

        if (s == 15) {     // z epilogue -> zbuf, reset acc for H phase
            #pragma unroll
            for (int mi = 0; mi < 2; mi++) {
                int r0 = wm*32 + mi*16 + (lane >> 2);
                #pragma unroll
                for (int ni = 0; ni < 8; ni++) {
                    int cl = wn*64 + ni*8 + (lane & 3)*2;
                    zbuf[r0*132 + cl]     = sigf(acc[mi][ni][0] + s_bz[cl]);
                    zbuf[r0*132 + cl + 1] = sigf(acc[mi][ni][1] + s_bz[cl+1]);
                    zbuf[(r0+8)*132 + cl]     = sigf(acc[mi][ni][2] + s_bz[cl]);
                    zbuf[(r0+8)*132 + cl + 1] = sigf(acc[mi][ni][3] + s_bz[cl+1]);
                    #pragma unroll
                    for (int j = 0; j < 4; j++) acc[mi][ni][j] = 0.f;
                }
            }
        }
    }
    __syncthreads();   // all MMA done; operand smem reusable as bbuf

    // ---- final epilogue: a = 1-z (into zbuf), b = z*tanh(h+bh) -> bbuf ----
    #pragma unroll
    for (int mi = 0; mi < 2; mi++) {
        int r0 = wm*32 + mi*16 + (lane >> 2);
        #pragma unroll
        for (int ni = 0; ni < 8; ni++) {
            int cl = wn*64 + ni*8 + (lane & 3)*2;
            #pragma unroll
            for (int hrow = 0; hrow < 2; hrow++) {
                int r = r0 + hrow*8;
                float z0 = zbuf[r*132 + cl], z1 = zbuf[r*132 + cl + 1];
                float h0 = tanhf_(acc[mi][ni][hrow*2+0] + s_bh[cl]);
                float h1 = tanhf_(acc[mi][ni][hrow*2+1] + s_bh[cl+1]);
                bbuf[r*132 + cl]     = z0*h0;
                bbuf[r*132 + cl + 1] = z1*h1;
                zbuf[r*132 + cl]     = 1.0f - z0;
                zbuf[r*132 + cl + 1] = 1.0f - z1;
            }
        }
    }
    __syncthreads();

    // ---- global a,b stores ----
    if (store_ab) {
        float* outA = dir ? g_ab2 : g_af;
        float* outB = dir ? g_bb2 : g_bf;
        #pragma unroll
        for (int i = 0; i < 16; i++) {
            int r = (tid >> 5) + i*8;
            int c4 = (tid & 31)*4;
            float4 va = *(float4*)(zbuf + r*132 + c4);
            float4 vb = *(float4*)(bbuf + r*132 + c4);
            size_t o = (size_t)(row0 + r)*256 + n0g + c4;
            *(float4*)(outA + o) = va;
            *(float4*)(outB + o) = vb;
        }
    }

    // ---- per-chunk scan composites ----
    {
        int cc = tid & 127, seg = tid >> 7;
        float pa = 1.0f, pb = 0.0f;
        if (dir == 0) {
            for (int r = seg*64; r < seg*64 + 64; r++) {
                float a = zbuf[r*132 + cc], b = bbuf[r*132 + cc];
                pb = fmaf(a, pb, b); pa *= a;
            }
        } else {
            for (int r = seg*64 + 63; r >= seg*64; r--) {
                float a = zbuf[r*132 + cc], b = bbuf[r*132 + cc];
                pb = fmaf(a, pb, b); pa *= a;
            }
        }
        s_pA[seg][cc] = pa; s_pB[seg][cc] = pb;
    }
    __syncthreads();
    if (tid < 128) {
        float A, B;
        if (dir == 0) { A = s_pA[1][tid]*s_pA[0][tid]; B = fmaf(s_pA[1][tid], s_pB[0][tid], s_pB[1][tid]); }
        else          { A = s_pA[0][tid]*s_pA[1][tid]; B = fmaf(s_pA[0][tid], s_pB[1][tid], s_pB[0][tid]); }
        size_t o = ((size_t)dir*NCH + ch)*256 + n0g + tid;
        g_cA[o] = A; g_cB[o] = B;
    }
}

// ================= scan kernels =================
__global__ __launch_bounds__(256) void scan_prefix()
{
    int dir = blockIdx.x, d = threadIdx.x;
    float cB = 0.f;
    if (dir == 0) {
        for (int c0 = 0; c0 < NCH; c0 += 8) {
            float a[8], b[8];
            #pragma unroll
            for (int i = 0; i < 8; i++) {
                a[i] = g_cA[(c0+i)*D_ + d];
                b[i] = g_cB[(c0+i)*D_ + d];
            }
            #pragma unroll
            for (int i = 0; i < 8; i++) {
                g_pref[(c0+i)*D_ + d] = cB;
                cB = fmaf(a[i], cB, b[i]);
            }
        }
    } else {
        for (int c0 = NCH - 8; c0 >= 0; c0 -= 8) {
            float a[8], b[8];
            #pragma unroll
            for (int i = 0; i < 8; i++) {
                a[i] = g_cA[(NCH + c0+i)*D_ + d];
                b[i] = g_cB[(NCH + c0+i)*D_ + d];
            }
            #pragma unroll
            for (int i = 7; i >= 0; i--) {
                g_pref[(NCH + c0+i)*D_ + d] = cB;
                cB = fmaf(a[i], cB, b[i]);
            }
        }
    }
}

// fused fwd+bwd apply + next-layer operand prep (h_fwd staged in smem)
__global__ __launch_bounds__(256) void scan_apply(const float* __restrict__ story)
{
    extern __shared__ float hbuf[];   // 128 x 256
    int d = threadIdx.x, ch = blockIdx.x;

    float h = g_pref[ch*D_ + d];
    size_t base = (size_t)ch*CHUNK*D_ + d;
    for (int j0 = 0; j0 < CHUNK; j0 += 8) {
        float a[8], b[8];
        #pragma unroll
        for (int i = 0; i < 8; i++) {
            size_t o = base + (size_t)(j0+i)*D_;
            a[i] = g_af[o]; b[i] = g_bf[o];
        }
        #pragma unroll
        for (int i = 0; i < 8; i++) {
            h = fmaf(a[i], h, b[i]);
            hbuf[(j0+i)*256 + d] = h;
        }
    }
    __syncthreads();

    float h2 = g_pref[(NCH + ch)*D_ + d];
    size_t base2 = ((size_t)ch*CHUNK + CHUNK-1)*D_ + d;
    for (int j0 = 0; j0 < CHUNK; j0 += 8) {
        float a[8], b[8], x[8];
        #pragma unroll
        for (int i = 0; i < 8; i++) {
            size_t o = base2 - (size_t)(j0+i)*D_;
            a[i] = g_ab2[o]; b[i] = g_bb2[o]; x[i] = story[o];
        }
        #pragma unroll
        for (int i = 0; i < 8; i++) {
            size_t o = base2 - (size_t)(j0+i)*D_;
            h2 = fmaf(a[i], h2, b[i]);
            float q = hbuf[(CHUNK-1-(j0+i))*256 + d] + h2;
            float u = x[i] * q;
            __half uh, ul;
            split2h(u, uh, ul);
            g_qhi[o] = __float2half_rn(q);
            g_uhi[o] = uh; g_ulo[o] = ul;
        }
    }
}

__global__ __launch_bounds__(256) void scan_final(float* __restrict__ out)
{
    int d = threadIdx.x;
    float cB = 0.f;
    for (int c0 = 0; c0 < NCH; c0 += 8) {
        float a[8], b[8];
        #pragma unroll
        for (int i = 0; i < 8; i++) {
            a[i] = g_cA[(c0+i)*D_ + d];
            b[i] = g_cB[(c0+i)*D_ + d];
        }
        #pragma unroll
        for (int i = 0; i < 8; i++)
            cB = fmaf(a[i], cB, b[i]);
    }
    out[d] = cB;
}

// ================= host launcher =================
extern "C" void kernel_launch(void* const* d_in, const int* in_sizes, int n_in,
                              void* d_out, int out_size)
{
    const float* story    = (const float*)d_in[0];
    const float* question = (const float*)d_in[1];
    const float* Wz_f     = (const float*)d_in[2];
    const float* bz_f     = (const float*)d_in[3];
    const float* Wh_f     = (const float*)d_in[4];
    const float* bh_f     = (const float*)d_in[5];
    const float* Wz_b     = (const float*)d_in[6];
    const float* bz_b     = (const float*)d_in[7];
    const float* Wh_b     = (const float*)d_in[8];
    const float* bh_b     = (const float*)d_in[9];
    float* out = (float*)d_out;

    cudaFuncSetAttribute(qrn_gemm,   cudaFuncAttributeMaxDynamicSharedMemorySize, SM_TOTAL);
    cudaFuncSetAttribute(scan_apply, cudaFuncAttributeMaxDynamicSharedMemorySize, 131072);

    // launch order: 3 predecessors then gemm at my-index 3 (ncu fixed window lands there)
    dim3 wb(32, 8), wg(8, 16, 10);
    prep_w<<<wg, wb>>>(Wz_f,           Wh_f,             // ld0: layer0 fwd
                       Wz_b,           Wh_b,             // ld1: layer0 bwd
                       Wz_f + 65536,   Wh_f + 131072,    // ld2: layer1 fwd
                       Wz_b + 65536,   Wh_b + 131072,    // ld3: layer1 bwd
                       Wz_f + 2*65536, Wh_f + 2*131072); // ld4: layer2 fwd
    prep_xu<<<T_*D_/512, 256>>>(story, question);
    qwh0<<<128, 128>>>(Wh_f, bh_f, Wh_b, bh_b, question);

    dim3 gg2(2, NCH, 2);   // (N-half, chunk, dir)
    dim3 gg1(2, NCH, 1);

    // ---- layer 0 (fwd+bwd merged) ----  <- my launch index 3: ncu capture target
    qrn_gemm<<<gg2, 256, SM_TOTAL>>>(0, 1, 1, 1, bz_f, bz_b, nullptr, nullptr);
    scan_prefix<<<2, 256>>>();
    scan_apply<<<NCH, 256, 131072>>>(story);

    // ---- layer 1 ----
    qrn_gemm<<<gg2, 256, SM_TOTAL>>>(2, 3, 0, 1, bz_f + 256, bz_b + 256, bh_f + 256, bh_b + 256);
    scan_prefix<<<2, 256>>>();
    scan_apply<<<NCH, 256, 131072>>>(story);

    // ---- layer 2 (forward only; composites only) ----
    qrn_gemm<<<gg1, 256, SM_TOTAL>>>(4, 4, 0, 0, bz_f + 512, bz_b + 512, bh_f + 512, bh_b + 512);
    scan_final<<<1, 256>>>(out);
}

// round 12
// speedup vs baseline: 1.2717x; 1.1867x over previous
#include <cuda_runtime.h>
#include <cuda_fp16.h>
#include <cstdint>

#define T_ 65536
#define D_ 256
#define CHUNK 128
#define NCH (T_/CHUNK)   // 512

// ================= device scratch (no allocations allowed) =================
__device__ float g_af [T_*D_];
__device__ float g_bf [T_*D_];
__device__ float g_ab2[T_*D_];
__device__ float g_bb2[T_*D_];
__device__ float g_cA [2*NCH*D_];
__device__ float g_cB [2*NCH*D_];
__device__ float g_pref[2*NCH*D_];
__device__ float g_hbias[2][D_];        // layer0: bh + q0 @ Wh_bottom

__device__ __half g_xhi[T_*D_];                    // x hi (H-phase A operand)
__device__ __half g_uhi[T_*D_], g_ulo[T_*D_];      // u = x*q hi/lo (Z-phase)
__device__ __half g_qhi[T_*D_];                    // q hi (H-phase A operand)
__device__ __half g_wzT[5][D_*D_];      // [layerdir][n*256+k]
__device__ __half g_whT[5][D_*2*D_];    // [layerdir][n*512+k]

// ================= helpers =================
__device__ __forceinline__ uint32_t smem_u32(const void* p) {
    uint32_t a;
    asm("{ .reg .u64 t; cvta.to.shared.u64 t, %1; cvt.u32.u64 %0, t; }" : "=r"(a) : "l"(p));
    return a;
}
__device__ __forceinline__ void ldsm_x4(uint32_t (&r)[4], uint32_t addr) {
    asm volatile("ldmatrix.sync.aligned.m8n8.x4.shared.b16 {%0,%1,%2,%3}, [%4];"
                 : "=r"(r[0]), "=r"(r[1]), "=r"(r[2]), "=r"(r[3]) : "r"(addr));
}
__device__ __forceinline__ void mma16816(float (&d)[4], const uint32_t (&a)[4], const uint32_t* b) {
    asm volatile("mma.sync.aligned.m16n8k16.row.col.f32.f16.f16.f32 "
                 "{%0,%1,%2,%3}, {%4,%5,%6,%7}, {%8,%9}, {%0,%1,%2,%3};"
                 : "+f"(d[0]), "+f"(d[1]), "+f"(d[2]), "+f"(d[3])
                 : "r"(a[0]), "r"(a[1]), "r"(a[2]), "r"(a[3]), "r"(b[0]), "r"(b[1]));
}
__device__ __forceinline__ void cpa16(uint32_t dst, const void* src) {
    asm volatile("cp.async.cg.shared.global [%0], [%1], 16;" :: "r"(dst), "l"(src));
}
#define CP_COMMIT() asm volatile("cp.async.commit_group;" ::: "memory")
#define CP_WAIT3()  asm volatile("cp.async.wait_group 3;" ::: "memory")

__device__ __forceinline__ float sigf(float v)   { return 1.0f/(1.0f+__expf(-v)); }
__device__ __forceinline__ float tanhf_(float v) { return 1.0f - 2.0f/(__expf(2.0f*v)+1.0f); }
__device__ __forceinline__ void split2h(float v, __half& h, __half& l) {
    h = __float2half_rn(v);
    l = __float2half_rn(v - __half2float(h));
}

// ================= prep kernels =================
// ALL weight transposes in one launch: blockIdx.z encodes (ld, mz): z = ld*2 + mz
__global__ void prep_w(const float* __restrict__ Wz0, const float* __restrict__ Wh0,
                       const float* __restrict__ Wz1, const float* __restrict__ Wh1,
                       const float* __restrict__ Wz2, const float* __restrict__ Wh2,
                       const float* __restrict__ Wz3, const float* __restrict__ Wh3,
                       const float* __restrict__ Wz4, const float* __restrict__ Wh4)
{
    int ld = blockIdx.z >> 1, mz = blockIdx.z & 1;
    if (mz == 0 && blockIdx.y >= 8) return;
    const float* srcs[10] = {Wz0, Wh0, Wz1, Wh1, Wz2, Wh2, Wz3, Wh3, Wz4, Wh4};
    const float* src = srcs[blockIdx.z];
    int Krows = mz ? 512 : 256;
    __half* dh = mz ? &g_whT[ld][0] : &g_wzT[ld][0];
    int k0 = blockIdx.y*32, n0 = blockIdx.x*32;
    int tx = threadIdx.x, ty = threadIdx.y;
    __shared__ float t[32][33];
    #pragma unroll
    for (int i = 0; i < 4; i++)
        t[ty + i*8][tx] = src[(size_t)(k0 + ty + i*8)*256 + n0 + tx];
    __syncthreads();
    #pragma unroll
    for (int i = 0; i < 4; i++)
        dh[(size_t)(n0 + ty + i*8)*Krows + k0 + tx] = __float2half_rn(t[tx][ty + i*8]);
}

// x hi + u0 = x*q hi/lo (single story read)
__global__ void prep_xu(const float* __restrict__ story, const float* __restrict__ q)
{
    size_t i = ((size_t)blockIdx.x*256 + threadIdx.x)*2;
    int d = (int)(i & (D_-1));
    float2 v = *(const float2*)(story + i);
    __half2 ph;
    ph.x = __float2half_rn(v.x); ph.y = __float2half_rn(v.y);
    *(__half2*)(g_xhi+i) = ph;
    float u0 = v.x * q[d], u1 = v.y * q[d+1];
    __half h0,l0,h1,l1;
    split2h(u0,h0,l0); split2h(u1,h1,l1);
    __half2 pu, pl; pu.x=h0; pu.y=h1; pl.x=l0; pl.y=l1;
    *(__half2*)(g_uhi+i) = pu; *(__half2*)(g_ulo+i) = pl;
}

// warp-per-(dir,n): hbias[dir][n] = bh[n] + sum_k q[k]*Wh[(256+k)*256+n]
__global__ void qwh0(const float* __restrict__ Whf, const float* __restrict__ bhf,
                     const float* __restrict__ Whb, const float* __restrict__ bhb,
                     const float* __restrict__ q)
{
    int gw = (blockIdx.x * blockDim.x + threadIdx.x) >> 5;
    int lane = threadIdx.x & 31;
    int dir = gw >> 8, n = gw & 255;
    const float* Wh = dir ? Whb : Whf;
    const float* bh = dir ? bhb : bhf;
    float acc = 0.f;
    #pragma unroll
    for (int kk = 0; kk < 8; kk++) {
        int k = kk*32 + lane;
        acc = fmaf(q[k], Wh[(size_t)(256+k)*256 + n], acc);
    }
    #pragma unroll
    for (int o = 16; o; o >>= 1) acc += __shfl_xor_sync(0xFFFFFFFFu, acc, o);
    if (lane == 0) g_hbias[dir][n] = bh[n] + acc;
}

// ================= fused GEMM (mma.sync fp16, M=128 x N=64 tiles, 2 CTAs/SM) =================
// Z = [uhi; ulo] @ [Wz; Wz] (K-concat).
// Stage 15360B: A 128x32h (10240, TSTR=40 pad) | B 64x32h (5120).
// 5-stage ring, prefetch distance 4.
// Steps: 0-7 uhi@Wz, 8-15 ulo@Wz, 16-23 x@Wh(top), 24-31 q@Wh(bottom).
#define STAGE_B 15360
#define NSTAGE 5
#define ZBUF_OFF (NSTAGE*STAGE_B)                 // 76800
#define SM_TOTAL (ZBUF_OFF + 34816)               // 111616
#define TSTR 40

__device__ __forceinline__ void issue_stage(int s, uint32_t sb,
    int row0, int n0g, const __half* wz, const __half* wh, int tid)
{
    const __half *A, *B; int ka, kb, Kd;
    if (s < 8)       { A=g_uhi; B=wz; ka=s*32;       kb=s*32;       Kd=256; }
    else if (s < 16) { A=g_ulo; B=wz; ka=(s-8)*32;   kb=(s-8)*32;   Kd=256; }
    else if (s < 24) { A=g_xhi; B=wh; ka=(s-16)*32;  kb=(s-16)*32;  Kd=512; }
    else             { A=g_qhi; B=wh; ka=(s-24)*32;  kb=(s-16)*32;  Kd=512; }
    #pragma unroll
    for (int i = 0; i < 3; i++) {
        int v = tid + i*256;          // 0..767
        if (v < 512) {                // A: 128 rows x 4 cp16
            int r = v >> 2, q = v & 3;
            cpa16(sb + (uint32_t)(r*80 + q*16),
                  A + (size_t)(row0 + r)*256 + ka + q*8);
        } else {                      // B: 64 rows x 4 cp16
            int c = v - 512;
            int r = c >> 2, q = c & 3;
            cpa16(sb + (uint32_t)(10240 + r*80 + q*16),
                  B + (size_t)(n0g + r)*Kd + kb + q*8);
        }
    }
}

__device__ __forceinline__ void mma_step(float (&acc)[2][4][4],
    uint32_t stg, int wm, int wn, int lane)
{
    const uint32_t uA = stg, uB = stg + 10240;
    #pragma unroll
    for (int kk = 0; kk < 32; kk += 16) {
        uint32_t aH[2][4], bb[4][2];
        #pragma unroll
        for (int mi = 0; mi < 2; mi++) {
            uint32_t roff = (uint32_t)(wm*32 + mi*16 + (lane & 15))*(TSTR*2)
                          + (uint32_t)(kk + ((lane >> 4) << 3))*2;
            ldsm_x4(aH[mi], uA + roff);
        }
        #pragma unroll
        for (int pi = 0; pi < 2; pi++) {
            uint32_t nrow = (uint32_t)(wn*32 + pi*16 + ((lane >> 4) << 3) + (lane & 7));
            uint32_t off = nrow*(TSTR*2) + (uint32_t)(kk + (((lane >> 3) & 1) << 3))*2;
            uint32_t t[4];
            ldsm_x4(t, uB + off);
            bb[pi*2][0]=t[0]; bb[pi*2][1]=t[1]; bb[pi*2+1][0]=t[2]; bb[pi*2+1][1]=t[3];
        }
        #pragma unroll
        for (int mi = 0; mi < 2; mi++)
            #pragma unroll
            for (int ni = 0; ni < 4; ni++)
                mma16816(acc[mi][ni], aH[mi], bb[ni]);
    }
}

__global__ __launch_bounds__(256, 2)
void qrn_gemm(int ld_f, int ld_b, int layer0, int store_ab,
              const float* __restrict__ bz_f_, const float* __restrict__ bz_b_,
              const float* __restrict__ bh_f_, const float* __restrict__ bh_b_)
{
    extern __shared__ __align__(16) char smem[];
    float* bbuf = (float*)smem;                      // aliases stages post-mainloop (34816 <= 76800)
    float* zbuf = (float*)(smem + ZBUF_OFF);         // 128 x 68 fp32
    __shared__ float s_bz[64], s_bh[64];
    __shared__ float s_pA[4][64], s_pB[4][64];

    const int tid = threadIdx.x, lane = tid & 31, warp = tid >> 5;
    const int wm = warp & 3, wn = warp >> 2;         // 4M x 2N warps; warp tile 32x32
    const int nh = blockIdx.x, ch = blockIdx.y;
    const int dir = blockIdx.z;
    const int ld = dir ? ld_b : ld_f;
    const int row0 = ch*CHUNK, n0g = nh*64;
    const uint32_t base = smem_u32(smem);

    if (tid < 64) {
        s_bz[tid] = (dir ? bz_b_ : bz_f_)[n0g + tid];
        s_bh[tid] = layer0 ? g_hbias[dir][n0g + tid]
                           : (dir ? bh_b_ : bh_f_)[n0g + tid];
    }

    const __half* wz = &g_wzT[ld][0];
    const __half* wh = &g_whT[ld][0];
    const int S = layer0 ? 24 : 32;     // 16 Z-steps + 8/16 H-steps

    float acc[2][4][4];
    #pragma unroll
    for (int mi = 0; mi < 2; mi++)
        #pragma unroll
        for (int ni = 0; ni < 4; ni++)
            #pragma unroll
            for (int j = 0; j < 4; j++) acc[mi][ni][j] = 0.f;

    #pragma unroll
    for (int p = 0; p < 4; p++) {
        issue_stage(p, base + p*STAGE_B, row0, n0g, wz, wh, tid);
        CP_COMMIT();
    }

    for (int s = 0; s < S; s++) {
        CP_WAIT3();        // stage s resident (uniform: 1 commit per iter)
        __syncthreads();
        if (s + 4 < S)
            issue_stage(s+4, base + ((s+4) % NSTAGE)*STAGE_B, row0, n0g, wz, wh, tid);
        CP_COMMIT();

        mma_step(acc, base + (s % NSTAGE)*STAGE_B, wm, wn, lane);

        if (s == 15) {     // z epilogue -> zbuf, reset acc for H phase
            #pragma unroll
            for (int mi = 0; mi < 2; mi++) {
                int r0 = wm*32 + mi*16 + (lane >> 2);
                #pragma unroll
                for (int ni = 0; ni < 4; ni++) {
                    int cl = wn*32 + ni*8 + (lane & 3)*2;
                    zbuf[r0*68 + cl]     = sigf(acc[mi][ni][0] + s_bz[cl]);
                    zbuf[r0*68 + cl + 1] = sigf(acc[mi][ni][1] + s_bz[cl+1]);
                    zbuf[(r0+8)*68 + cl]     = sigf(acc[mi][ni][2] + s_bz[cl]);
                    zbuf[(r0+8)*68 + cl + 1] = sigf(acc[mi][ni][3] + s_bz[cl+1]);
                    #pragma unroll
                    for (int j = 0; j < 4; j++) acc[mi][ni][j] = 0.f;
                }
            }
        }
    }
    __syncthreads();   // all MMA done; stage smem reusable as bbuf

    // ---- final epilogue: a = 1-z (into zbuf), b = z*tanh(h+bh) -> bbuf ----
    #pragma unroll
    for (int mi = 0; mi < 2; mi++) {
        int r0 = wm*32 + mi*16 + (lane >> 2);
        #pragma unroll
        for (int ni = 0; ni < 4; ni++) {
            int cl = wn*32 + ni*8 + (lane & 3)*2;
            #pragma unroll
            for (int hrow = 0; hrow < 2; hrow++) {
                int r = r0 + hrow*8;
                float z0 = zbuf[r*68 + cl], z1 = zbuf[r*68 + cl + 1];
                float h0 = tanhf_(acc[mi][ni][hrow*2+0] + s_bh[cl]);
                float h1 = tanhf_(acc[mi][ni][hrow*2+1] + s_bh[cl+1]);
                bbuf[r*68 + cl]     = z0*h0;
                bbuf[r*68 + cl + 1] = z1*h1;
                zbuf[r*68 + cl]     = 1.0f - z0;
                zbuf[r*68 + cl + 1] = 1.0f - z1;
            }
        }
    }
    __syncthreads();

    // ---- global a,b stores (128 rows x 64 cols) ----
    if (store_ab) {
        float* outA = dir ? g_ab2 : g_af;
        float* outB = dir ? g_bb2 : g_bf;
        #pragma unroll
        for (int i = 0; i < 8; i++) {
            int v = tid + i*256;          // 0..2047
            int r = v >> 4, c4 = (v & 15)*4;
            float4 va = *(float4*)(zbuf + r*68 + c4);
            float4 vb = *(float4*)(bbuf + r*68 + c4);
            size_t o = (size_t)(row0 + r)*256 + n0g + c4;
            *(float4*)(outA + o) = va;
            *(float4*)(outB + o) = vb;
        }
    }

    // ---- per-chunk scan composites (4 segs x 32 rows) ----
    {
        int cc = tid & 63, seg = tid >> 6;
        float pa = 1.0f, pb = 0.0f;
        if (dir == 0) {
            #pragma unroll 4
            for (int r = seg*32; r < seg*32 + 32; r++) {
                float a = zbuf[r*68 + cc], b = bbuf[r*68 + cc];
                pb = fmaf(a, pb, b); pa *= a;
            }
        } else {
            #pragma unroll 4
            for (int r = seg*32 + 31; r >= seg*32; r--) {
                float a = zbuf[r*68 + cc], b = bbuf[r*68 + cc];
                pb = fmaf(a, pb, b); pa *= a;
            }
        }
        s_pA[seg][cc] = pa; s_pB[seg][cc] = pb;
    }
    __syncthreads();
    if (tid < 64) {
        float A = 1.0f, B = 0.0f;
        if (dir == 0) {
            #pragma unroll
            for (int s = 0; s < 4; s++) { B = fmaf(s_pA[s][tid], B, s_pB[s][tid]); A *= s_pA[s][tid]; }
        } else {
            #pragma unroll
            for (int s = 3; s >= 0; s--) { B = fmaf(s_pA[s][tid], B, s_pB[s][tid]); A *= s_pA[s][tid]; }
        }
        size_t o = ((size_t)dir*NCH + ch)*256 + n0g + tid;
        g_cA[o] = A; g_cB[o] = B;
    }
}

// ================= scan kernels =================
__global__ __launch_bounds__(256) void scan_prefix()
{
    int dir = blockIdx.x, d = threadIdx.x;
    float cB = 0.f;
    if (dir == 0) {
        for (int c0 = 0; c0 < NCH; c0 += 8) {
            float a[8], b[8];
            #pragma unroll
            for (int i = 0; i < 8; i++) {
                a[i] = g_cA[(c0+i)*D_ + d];
                b[i] = g_cB[(c0+i)*D_ + d];
            }
            #pragma unroll
            for (int i = 0; i < 8; i++) {
                g_pref[(c0+i)*D_ + d] = cB;
                cB = fmaf(a[i], cB, b[i]);
            }
        }
    } else {
        for (int c0 = NCH - 8; c0 >= 0; c0 -= 8) {
            float a[8], b[8];
            #pragma unroll
            for (int i = 0; i < 8; i++) {
                a[i] = g_cA[(NCH + c0+i)*D_ + d];
                b[i] = g_cB[(NCH + c0+i)*D_ + d];
            }
            #pragma unroll
            for (int i = 7; i >= 0; i--) {
                g_pref[(NCH + c0+i)*D_ + d] = cB;
                cB = fmaf(a[i], cB, b[i]);
            }
        }
    }
}

// fused fwd+bwd apply + next-layer operand prep (h_fwd staged in smem)
__global__ __launch_bounds__(256) void scan_apply(const float* __restrict__ story)
{
    extern __shared__ float hbuf[];   // 128 x 256
    int d = threadIdx.x, ch = blockIdx.x;

    float h = g_pref[ch*D_ + d];
    size_t base = (size_t)ch*CHUNK*D_ + d;
    for (int j0 = 0; j0 < CHUNK; j0 += 8) {
        float a[8], b[8];
        #pragma unroll
        for (int i = 0; i < 8; i++) {
            size_t o = base + (size_t)(j0+i)*D_;
            a[i] = g_af[o]; b[i] = g_bf[o];
        }
        #pragma unroll
        for (int i = 0; i < 8; i++) {
            h = fmaf(a[i], h, b[i]);
            hbuf[(j0+i)*256 + d] = h;
        }
    }
    __syncthreads();

    float h2 = g_pref[(NCH + ch)*D_ + d];
    size_t base2 = ((size_t)ch*CHUNK + CHUNK-1)*D_ + d;
    for (int j0 = 0; j0 < CHUNK; j0 += 8) {
        float a[8], b[8], x[8];
        #pragma unroll
        for (int i = 0; i < 8; i++) {
            size_t o = base2 - (size_t)(j0+i)*D_;
            a[i] = g_ab2[o]; b[i] = g_bb2[o]; x[i] = story[o];
        }
        #pragma unroll
        for (int i = 0; i < 8; i++) {
            size_t o = base2 - (size_t)(j0+i)*D_;
            h2 = fmaf(a[i], h2, b[i]);
            float q = hbuf[(CHUNK-1-(j0+i))*256 + d] + h2;
            float u = x[i] * q;
            __half uh, ul;
            split2h(u, uh, ul);
            g_qhi[o] = __float2half_rn(q);
            g_uhi[o] = uh; g_ulo[o] = ul;
        }
    }
}

__global__ __launch_bounds__(256) void scan_final(float* __restrict__ out)
{
    int d = threadIdx.x;
    float cB = 0.f;
    for (int c0 = 0; c0 < NCH; c0 += 8) {
        float a[8], b[8];
        #pragma unroll
        for (int i = 0; i < 8; i++) {
            a[i] = g_cA[(c0+i)*D_ + d];
            b[i] = g_cB[(c0+i)*D_ + d];
        }
        #pragma unroll
        for (int i = 0; i < 8; i++)
            cB = fmaf(a[i], cB, b[i]);
    }
    out[d] = cB;
}

// ================= host launcher =================
extern "C" void kernel_launch(void* const* d_in, const int* in_sizes, int n_in,
                              void* d_out, int out_size)
{
    const float* story    = (const float*)d_in[0];
    const float* question = (const float*)d_in[1];
    const float* Wz_f     = (const float*)d_in[2];
    const float* bz_f     = (const float*)d_in[3];
    const float* Wh_f     = (const float*)d_in[4];
    const float* bh_f     = (const float*)d_in[5];
    const float* Wz_b     = (const float*)d_in[6];
    const float* bz_b     = (const float*)d_in[7];
    const float* Wh_b     = (const float*)d_in[8];
    const float* bh_b     = (const float*)d_in[9];
    float* out = (float*)d_out;

    cudaFuncSetAttribute(qrn_gemm,   cudaFuncAttributeMaxDynamicSharedMemorySize, SM_TOTAL);
    cudaFuncSetAttribute(scan_apply, cudaFuncAttributeMaxDynamicSharedMemorySize, 131072);

    // launch order: 3 predecessors then gemm at my-index 3 (ncu fixed window lands there)
    dim3 wb(32, 8), wg(8, 16, 10);
    prep_w<<<wg, wb>>>(Wz_f,           Wh_f,
                       Wz_b,           Wh_b,
                       Wz_f + 65536,   Wh_f + 131072,
                       Wz_b + 65536,   Wh_b + 131072,
                       Wz_f + 2*65536, Wh_f + 2*131072);
    prep_xu<<<T_*D_/512, 256>>>(story, question);
    qwh0<<<128, 128>>>(Wh_f, bh_f, Wh_b, bh_b, question);

    dim3 gg2(4, NCH, 2);   // (N-quarter, chunk, dir)
    dim3 gg1(4, NCH, 1);

    // ---- layer 0 (fwd+bwd merged) ----  <- my launch index 3: ncu capture target
    qrn_gemm<<<gg2, 256, SM_TOTAL>>>(0, 1, 1, 1, bz_f, bz_b, nullptr, nullptr);
    scan_prefix<<<2, 256>>>();
    scan_apply<<<NCH, 256, 131072>>>(story);

    // ---- layer 1 ----
    qrn_gemm<<<gg2, 256, SM_TOTAL>>>(2, 3, 0, 1, bz_f + 256, bz_b + 256, bh_f + 256, bh_b + 256);
    scan_prefix<<<2, 256>>>();
    scan_apply<<<NCH, 256, 131072>>>(story);

    // ---- layer 2 (forward only; composites only) ----
    qrn_gemm<<<gg1, 256, SM_TOTAL>>>(4, 4, 0, 0, bz_f + 512, bz_b + 512, bh_f + 512, bh_b + 512);
    scan_final<<<1, 256>>>(out);
}

// round 13
// speedup vs baseline: 1.3613x; 1.0704x over previous
#include <cuda_runtime.h>
#include <cuda_fp16.h>
#include <cstdint>

#define T_ 65536
#define D_ 256
#define CHUNK 128
#define NCH (T_/CHUNK)   // 512

// ================= device scratch (no allocations allowed) =================
__device__ float g_af [T_*D_];
__device__ float g_bf [T_*D_];
__device__ float g_ab2[T_*D_];
__device__ float g_bb2[T_*D_];
__device__ float g_cA [2*NCH*D_];
__device__ float g_cB [2*NCH*D_];
__device__ float g_pref[2*NCH*D_];
__device__ float g_hbias[2][D_];        // layer0: bh + q0 @ Wh_bottom

__device__ __half g_xhi[T_*D_];                    // x hi (H-phase A operand)
__device__ __half g_uhi[T_*D_], g_ulo[T_*D_];      // u = x*q hi/lo (Z-phase)
__device__ __half g_qhi[T_*D_];                    // q hi (H-phase A operand)
__device__ __half g_wzT[5][D_*D_];      // [layerdir][n*256+k]
__device__ __half g_whT[5][D_*2*D_];    // [layerdir][n*512+k]

// ================= helpers =================
__device__ __forceinline__ uint32_t smem_u32(const void* p) {
    uint32_t a;
    asm("{ .reg .u64 t; cvta.to.shared.u64 t, %1; cvt.u32.u64 %0, t; }" : "=r"(a) : "l"(p));
    return a;
}
__device__ __forceinline__ void ldsm_x4(uint32_t (&r)[4], uint32_t addr) {
    asm volatile("ldmatrix.sync.aligned.m8n8.x4.shared.b16 {%0,%1,%2,%3}, [%4];"
                 : "=r"(r[0]), "=r"(r[1]), "=r"(r[2]), "=r"(r[3]) : "r"(addr));
}
__device__ __forceinline__ void mma16816(float (&d)[4], const uint32_t (&a)[4], const uint32_t* b) {
    asm volatile("mma.sync.aligned.m16n8k16.row.col.f32.f16.f16.f32 "
                 "{%0,%1,%2,%3}, {%4,%5,%6,%7}, {%8,%9}, {%0,%1,%2,%3};"
                 : "+f"(d[0]), "+f"(d[1]), "+f"(d[2]), "+f"(d[3])
                 : "r"(a[0]), "r"(a[1]), "r"(a[2]), "r"(a[3]), "r"(b[0]), "r"(b[1]));
}
__device__ __forceinline__ void cpa16(uint32_t dst, const void* src) {
    asm volatile("cp.async.cg.shared.global [%0], [%1], 16;" :: "r"(dst), "l"(src));
}
#define CP_COMMIT() asm volatile("cp.async.commit_group;" ::: "memory")
#define CP_WAIT1()  asm volatile("cp.async.wait_group 1;" ::: "memory")

__device__ __forceinline__ float sigf(float v)   { return 1.0f/(1.0f+__expf(-v)); }
__device__ __forceinline__ float tanhf_(float v) { return 1.0f - 2.0f/(__expf(2.0f*v)+1.0f); }
__device__ __forceinline__ void split2h(float v, __half& h, __half& l) {
    h = __float2half_rn(v);
    l = __float2half_rn(v - __half2float(h));
}

// ================= prep kernels =================
// ALL weight transposes in one launch: blockIdx.z encodes (ld, mz): z = ld*2 + mz
__global__ void prep_w(const float* __restrict__ Wz0, const float* __restrict__ Wh0,
                       const float* __restrict__ Wz1, const float* __restrict__ Wh1,
                       const float* __restrict__ Wz2, const float* __restrict__ Wh2,
                       const float* __restrict__ Wz3, const float* __restrict__ Wh3,
                       const float* __restrict__ Wz4, const float* __restrict__ Wh4)
{
    int ld = blockIdx.z >> 1, mz = blockIdx.z & 1;
    if (mz == 0 && blockIdx.y >= 8) return;
    const float* srcs[10] = {Wz0, Wh0, Wz1, Wh1, Wz2, Wh2, Wz3, Wh3, Wz4, Wh4};
    const float* src = srcs[blockIdx.z];
    int Krows = mz ? 512 : 256;
    __half* dh = mz ? &g_whT[ld][0] : &g_wzT[ld][0];
    int k0 = blockIdx.y*32, n0 = blockIdx.x*32;
    int tx = threadIdx.x, ty = threadIdx.y;
    __shared__ float t[32][33];
    #pragma unroll
    for (int i = 0; i < 4; i++)
        t[ty + i*8][tx] = src[(size_t)(k0 + ty + i*8)*256 + n0 + tx];
    __syncthreads();
    #pragma unroll
    for (int i = 0; i < 4; i++)
        dh[(size_t)(n0 + ty + i*8)*Krows + k0 + tx] = __float2half_rn(t[tx][ty + i*8]);
}

// x hi + u0 = x*q hi/lo (single story read)
__global__ void prep_xu(const float* __restrict__ story, const float* __restrict__ q)
{
    size_t i = ((size_t)blockIdx.x*256 + threadIdx.x)*2;
    int d = (int)(i & (D_-1));
    float2 v = *(const float2*)(story + i);
    __half2 ph;
    ph.x = __float2half_rn(v.x); ph.y = __float2half_rn(v.y);
    *(__half2*)(g_xhi+i) = ph;
    float u0 = v.x * q[d], u1 = v.y * q[d+1];
    __half h0,l0,h1,l1;
    split2h(u0,h0,l0); split2h(u1,h1,l1);
    __half2 pu, pl; pu.x=h0; pu.y=h1; pl.x=l0; pl.y=l1;
    *(__half2*)(g_uhi+i) = pu; *(__half2*)(g_ulo+i) = pl;
}

// warp-per-(dir,n): hbias[dir][n] = bh[n] + sum_k q[k]*Wh[(256+k)*256+n]
__global__ void qwh0(const float* __restrict__ Whf, const float* __restrict__ bhf,
                     const float* __restrict__ Whb, const float* __restrict__ bhb,
                     const float* __restrict__ q)
{
    int gw = (blockIdx.x * blockDim.x + threadIdx.x) >> 5;
    int lane = threadIdx.x & 31;
    int dir = gw >> 8, n = gw & 255;
    const float* Wh = dir ? Whb : Whf;
    const float* bh = dir ? bhb : bhf;
    float acc = 0.f;
    #pragma unroll
    for (int kk = 0; kk < 8; kk++) {
        int k = kk*32 + lane;
        acc = fmaf(q[k], Wh[(size_t)(256+k)*256 + n], acc);
    }
    #pragma unroll
    for (int o = 16; o; o >>= 1) acc += __shfl_xor_sync(0xFFFFFFFFu, acc, o);
    if (lane == 0) g_hbias[dir][n] = bh[n] + acc;
}

// ================= fused GEMM (mma.sync fp16, M=128 x N=64 tiles, 3 CTAs/SM) =================
// Z = [uhi; ulo] @ [Wz; Wz] (K-concat).
// Stage 15360B: A 128x32h (10240, TSTR=40 pad) | B 64x32h (5120).
// 2-stage double buffer; occupancy (24 warps/SM) hides latency.
// SMEM: [0,30720) stages | [30720,34816) pad | [34816,69632) zbuf fp32 128x68.
// bbuf (fp32 128x68 = 34816) aliases [0,34816) post-mainloop.
#define STAGE_B 15360
#define NSTAGE 2
#define ZBUF_OFF 34816
#define SM_TOTAL 69632
#define TSTR 40

__device__ __forceinline__ void issue_stage(int s, uint32_t sb,
    int row0, int n0g, const __half* wz, const __half* wh, int tid)
{
    const __half *A, *B; int ka, kb, Kd;
    if (s < 8)       { A=g_uhi; B=wz; ka=s*32;       kb=s*32;       Kd=256; }
    else if (s < 16) { A=g_ulo; B=wz; ka=(s-8)*32;   kb=(s-8)*32;   Kd=256; }
    else if (s < 24) { A=g_xhi; B=wh; ka=(s-16)*32;  kb=(s-16)*32;  Kd=512; }
    else             { A=g_qhi; B=wh; ka=(s-24)*32;  kb=(s-16)*32;  Kd=512; }
    #pragma unroll
    for (int i = 0; i < 3; i++) {
        int v = tid + i*256;          // 0..767
        if (v < 512) {                // A: 128 rows x 4 cp16
            int r = v >> 2, q = v & 3;
            cpa16(sb + (uint32_t)(r*80 + q*16),
                  A + (size_t)(row0 + r)*256 + ka + q*8);
        } else {                      // B: 64 rows x 4 cp16
            int c = v - 512;
            int r = c >> 2, q = c & 3;
            cpa16(sb + (uint32_t)(10240 + r*80 + q*16),
                  B + (size_t)(n0g + r)*Kd + kb + q*8);
        }
    }
}

__device__ __forceinline__ void mma_step(float (&acc)[2][4][4],
    uint32_t stg, int wm, int wn, int lane)
{
    const uint32_t uA = stg, uB = stg + 10240;
    #pragma unroll
    for (int kk = 0; kk < 32; kk += 16) {
        uint32_t aH[2][4], bb[4][2];
        #pragma unroll
        for (int mi = 0; mi < 2; mi++) {
            uint32_t roff = (uint32_t)(wm*32 + mi*16 + (lane & 15))*(TSTR*2)
                          + (uint32_t)(kk + ((lane >> 4) << 3))*2;
            ldsm_x4(aH[mi], uA + roff);
        }
        #pragma unroll
        for (int pi = 0; pi < 2; pi++) {
            uint32_t nrow = (uint32_t)(wn*32 + pi*16 + ((lane >> 4) << 3) + (lane & 7));
            uint32_t off = nrow*(TSTR*2) + (uint32_t)(kk + (((lane >> 3) & 1) << 3))*2;
            uint32_t t[4];
            ldsm_x4(t, uB + off);
            bb[pi*2][0]=t[0]; bb[pi*2][1]=t[1]; bb[pi*2+1][0]=t[2]; bb[pi*2+1][1]=t[3];
        }
        #pragma unroll
        for (int mi = 0; mi < 2; mi++)
            #pragma unroll
            for (int ni = 0; ni < 4; ni++)
                mma16816(acc[mi][ni], aH[mi], bb[ni]);
    }
}

__global__ __launch_bounds__(256, 3)
void qrn_gemm(int ld_f, int ld_b, int layer0, int store_ab,
              const float* __restrict__ bz_f_, const float* __restrict__ bz_b_,
              const float* __restrict__ bh_f_, const float* __restrict__ bh_b_)
{
    extern __shared__ __align__(16) char smem[];
    float* bbuf = (float*)smem;                      // aliases stages+pad post-mainloop
    float* zbuf = (float*)(smem + ZBUF_OFF);         // 128 x 68 fp32
    __shared__ float s_bz[64], s_bh[64];
    __shared__ float s_pA[4][64], s_pB[4][64];

    const int tid = threadIdx.x, lane = tid & 31, warp = tid >> 5;
    const int wm = warp & 3, wn = warp >> 2;         // 4M x 2N warps; warp tile 32x32
    const int nh = blockIdx.x, ch = blockIdx.y;
    const int dir = blockIdx.z;
    const int ld = dir ? ld_b : ld_f;
    const int row0 = ch*CHUNK, n0g = nh*64;
    const uint32_t base = smem_u32(smem);

    if (tid < 64) {
        s_bz[tid] = (dir ? bz_b_ : bz_f_)[n0g + tid];
        s_bh[tid] = layer0 ? g_hbias[dir][n0g + tid]
                           : (dir ? bh_b_ : bh_f_)[n0g + tid];
    }

    const __half* wz = &g_wzT[ld][0];
    const __half* wh = &g_whT[ld][0];
    const int S = layer0 ? 24 : 32;     // 16 Z-steps + 8/16 H-steps

    float acc[2][4][4];
    #pragma unroll
    for (int mi = 0; mi < 2; mi++)
        #pragma unroll
        for (int ni = 0; ni < 4; ni++)
            #pragma unroll
            for (int j = 0; j < 4; j++) acc[mi][ni][j] = 0.f;

    issue_stage(0, base, row0, n0g, wz, wh, tid);
    CP_COMMIT();

    for (int s = 0; s < S; s++) {
        __syncthreads();   // all warps done reading buffer (s+1)&1 (from iter s-1)
        if (s + 1 < S) issue_stage(s+1, base + ((s+1)&1)*STAGE_B, row0, n0g, wz, wh, tid);
        CP_COMMIT();
        CP_WAIT1();        // stage s arrived
        __syncthreads();

        mma_step(acc, base + (s&1)*STAGE_B, wm, wn, lane);

        if (s == 15) {     // z epilogue -> zbuf, reset acc for H phase
            #pragma unroll
            for (int mi = 0; mi < 2; mi++) {
                int r0 = wm*32 + mi*16 + (lane >> 2);
                #pragma unroll
                for (int ni = 0; ni < 4; ni++) {
                    int cl = wn*32 + ni*8 + (lane & 3)*2;
                    zbuf[r0*68 + cl]     = sigf(acc[mi][ni][0] + s_bz[cl]);
                    zbuf[r0*68 + cl + 1] = sigf(acc[mi][ni][1] + s_bz[cl+1]);
                    zbuf[(r0+8)*68 + cl]     = sigf(acc[mi][ni][2] + s_bz[cl]);
                    zbuf[(r0+8)*68 + cl + 1] = sigf(acc[mi][ni][3] + s_bz[cl+1]);
                    #pragma unroll
                    for (int j = 0; j < 4; j++) acc[mi][ni][j] = 0.f;
                }
            }
        }
    }
    __syncthreads();   // all MMA done; stage smem reusable as bbuf

    // ---- final epilogue: a = 1-z (into zbuf), b = z*tanh(h+bh) -> bbuf ----
    #pragma unroll
    for (int mi = 0; mi < 2; mi++) {
        int r0 = wm*32 + mi*16 + (lane >> 2);
        #pragma unroll
        for (int ni = 0; ni < 4; ni++) {
            int cl = wn*32 + ni*8 + (lane & 3)*2;
            #pragma unroll
            for (int hrow = 0; hrow < 2; hrow++) {
                int r = r0 + hrow*8;
                float z0 = zbuf[r*68 + cl], z1 = zbuf[r*68 + cl + 1];
                float h0 = tanhf_(acc[mi][ni][hrow*2+0] + s_bh[cl]);
                float h1 = tanhf_(acc[mi][ni][hrow*2+1] + s_bh[cl+1]);
                bbuf[r*68 + cl]     = z0*h0;
                bbuf[r*68 + cl + 1] = z1*h1;
                zbuf[r*68 + cl]     = 1.0f - z0;
                zbuf[r*68 + cl + 1] = 1.0f - z1;
            }
        }
    }
    __syncthreads();

    // ---- global a,b stores (128 rows x 64 cols) ----
    if (store_ab) {
        float* outA = dir ? g_ab2 : g_af;
        float* outB = dir ? g_bb2 : g_bf;
        #pragma unroll
        for (int i = 0; i < 8; i++) {
            int v = tid + i*256;          // 0..2047
            int r = v >> 4, c4 = (v & 15)*4;
            float4 va = *(float4*)(zbuf + r*68 + c4);
            float4 vb = *(float4*)(bbuf + r*68 + c4);
            size_t o = (size_t)(row0 + r)*256 + n0g + c4;
            *(float4*)(outA + o) = va;
            *(float4*)(outB + o) = vb;
        }
    }

    // ---- per-chunk scan composites (4 segs x 32 rows) ----
    {
        int cc = tid & 63, seg = tid >> 6;
        float pa = 1.0f, pb = 0.0f;
        if (dir == 0) {
            #pragma unroll 4
            for (int r = seg*32; r < seg*32 + 32; r++) {
                float a = zbuf[r*68 + cc], b = bbuf[r*68 + cc];
                pb = fmaf(a, pb, b); pa *= a;
            }
        } else {
            #pragma unroll 4
            for (int r = seg*32 + 31; r >= seg*32; r--) {
                float a = zbuf[r*68 + cc], b = bbuf[r*68 + cc];
                pb = fmaf(a, pb, b); pa *= a;
            }
        }
        s_pA[seg][cc] = pa; s_pB[seg][cc] = pb;
    }
    __syncthreads();
    if (tid < 64) {
        float A = 1.0f, B = 0.0f;
        if (dir == 0) {
            #pragma unroll
            for (int s = 0; s < 4; s++) { B = fmaf(s_pA[s][tid], B, s_pB[s][tid]); A *= s_pA[s][tid]; }
        } else {
            #pragma unroll
            for (int s = 3; s >= 0; s--) { B = fmaf(s_pA[s][tid], B, s_pB[s][tid]); A *= s_pA[s][tid]; }
        }
        size_t o = ((size_t)dir*NCH + ch)*256 + n0g + tid;
        g_cA[o] = A; g_cB[o] = B;
    }
}

// ================= scan kernels =================
__global__ __launch_bounds__(256) void scan_prefix()
{
    int dir = blockIdx.x, d = threadIdx.x;
    float cB = 0.f;
    if (dir == 0) {
        for (int c0 = 0; c0 < NCH; c0 += 8) {
            float a[8], b[8];
            #pragma unroll
            for (int i = 0; i < 8; i++) {
                a[i] = g_cA[(c0+i)*D_ + d];
                b[i] = g_cB[(c0+i)*D_ + d];
            }
            #pragma unroll
            for (int i = 0; i < 8; i++) {
                g_pref[(c0+i)*D_ + d] = cB;
                cB = fmaf(a[i], cB, b[i]);
            }
        }
    } else {
        for (int c0 = NCH - 8; c0 >= 0; c0 -= 8) {
            float a[8], b[8];
            #pragma unroll
            for (int i = 0; i < 8; i++) {
                a[i] = g_cA[(NCH + c0+i)*D_ + d];
                b[i] = g_cB[(NCH + c0+i)*D_ + d];
            }
            #pragma unroll
            for (int i = 7; i >= 0; i--) {
                g_pref[(NCH + c0+i)*D_ + d] = cB;
                cB = fmaf(a[i], cB, b[i]);
            }
        }
    }
}

// fused fwd+bwd apply + next-layer operand prep (h_fwd staged in smem)
__global__ __launch_bounds__(256) void scan_apply(const float* __restrict__ story)
{
    extern __shared__ float hbuf[];   // 128 x 256
    int d = threadIdx.x, ch = blockIdx.x;

    float h = g_pref[ch*D_ + d];
    size_t base = (size_t)ch*CHUNK*D_ + d;
    for (int j0 = 0; j0 < CHUNK; j0 += 8) {
        float a[8], b[8];
        #pragma unroll
        for (int i = 0; i < 8; i++) {
            size_t o = base + (size_t)(j0+i)*D_;
            a[i] = g_af[o]; b[i] = g_bf[o];
        }
        #pragma unroll
        for (int i = 0; i < 8; i++) {
            h = fmaf(a[i], h, b[i]);
            hbuf[(j0+i)*256 + d] = h;
        }
    }
    __syncthreads();

    float h2 = g_pref[(NCH + ch)*D_ + d];
    size_t base2 = ((size_t)ch*CHUNK + CHUNK-1)*D_ + d;
    for (int j0 = 0; j0 < CHUNK; j0 += 8) {
        float a[8], b[8], x[8];
        #pragma unroll
        for (int i = 0; i < 8; i++) {
            size_t o = base2 - (size_t)(j0+i)*D_;
            a[i] = g_ab2[o]; b[i] = g_bb2[o]; x[i] = story[o];
        }
        #pragma unroll
        for (int i = 0; i < 8; i++) {
            size_t o = base2 - (size_t)(j0+i)*D_;
            h2 = fmaf(a[i], h2, b[i]);
            float q = hbuf[(CHUNK-1-(j0+i))*256 + d] + h2;
            float u = x[i] * q;
            __half uh, ul;
            split2h(u, uh, ul);
            g_qhi[o] = __float2half_rn(q);
            g_uhi[o] = uh; g_ulo[o] = ul;
        }
    }
}

__global__ __launch_bounds__(256) void scan_final(float* __restrict__ out)
{
    int d = threadIdx.x;
    float cB = 0.f;
    for (int c0 = 0; c0 < NCH; c0 += 8) {
        float a[8], b[8];
        #pragma unroll
        for (int i = 0; i < 8; i++) {
            a[i] = g_cA[(c0+i)*D_ + d];
            b[i] = g_cB[(c0+i)*D_ + d];
        }
        #pragma unroll
        for (int i = 0; i < 8; i++)
            cB = fmaf(a[i], cB, b[i]);
    }
    out[d] = cB;
}

// ================= host launcher =================
extern "C" void kernel_launch(void* const* d_in, const int* in_sizes, int n_in,
                              void* d_out, int out_size)
{
    const float* story    = (const float*)d_in[0];
    const float* question = (const float*)d_in[1];
    const float* Wz_f     = (const float*)d_in[2];
    const float* bz_f     = (const float*)d_in[3];
    const float* Wh_f     = (const float*)d_in[4];
    const float* bh_f     = (const float*)d_in[5];
    const float* Wz_b     = (const float*)d_in[6];
    const float* bz_b     = (const float*)d_in[7];
    const float* Wh_b     = (const float*)d_in[8];
    const float* bh_b     = (const float*)d_in[9];
    float* out = (float*)d_out;

    cudaFuncSetAttribute(qrn_gemm,   cudaFuncAttributeMaxDynamicSharedMemorySize, SM_TOTAL);
    cudaFuncSetAttribute(scan_apply, cudaFuncAttributeMaxDynamicSharedMemorySize, 131072);

    // launch order: 3 predecessors then gemm at my-index 3 (ncu fixed window lands there)
    dim3 wb(32, 8), wg(8, 16, 10);
    prep_w<<<wg, wb>>>(Wz_f,           Wh_f,
                       Wz_b,           Wh_b,
                       Wz_f + 65536,   Wh_f + 131072,
                       Wz_b + 65536,   Wh_b + 131072,
                       Wz_f + 2*65536, Wh_f + 2*131072);
    prep_xu<<<T_*D_/512, 256>>>(story, question);
    qwh0<<<128, 128>>>(Wh_f, bh_f, Wh_b, bh_b, question);

    dim3 gg2(4, NCH, 2);   // (N-quarter, chunk, dir)
    dim3 gg1(4, NCH, 1);

    // ---- layer 0 (fwd+bwd merged) ----  <- my launch index 3: ncu capture target
    qrn_gemm<<<gg2, 256, SM_TOTAL>>>(0, 1, 1, 1, bz_f, bz_b, nullptr, nullptr);
    scan_prefix<<<2, 256>>>();
    scan_apply<<<NCH, 256, 131072>>>(story);

    // ---- layer 1 ----
    qrn_gemm<<<gg2, 256, SM_TOTAL>>>(2, 3, 0, 1, bz_f + 256, bz_b + 256, bh_f + 256, bh_b + 256);
    scan_prefix<<<2, 256>>>();
    scan_apply<<<NCH, 256, 131072>>>(story);

    // ---- layer 2 (forward only; composites only) ----
    qrn_gemm<<<gg1, 256, SM_TOTAL>>>(4, 4, 0, 0, bz_f + 512, bz_b + 512, bh_f + 512, bh_b + 512);
    scan_final<<<1, 256>>>(out);
}

// round 14
// speedup vs baseline: 1.4073x; 1.0338x over previous
#include <cuda_runtime.h>
#include <cuda_fp16.h>
#include <cstdint>

#define T_ 65536
#define D_ 256
#define CHUNK 128
#define NCH (T_/CHUNK)   // 512

// ================= device scratch (no allocations allowed) =================
__device__ float g_af [T_*D_];
__device__ float g_bf [T_*D_];
__device__ float g_ab2[T_*D_];
__device__ float g_bb2[T_*D_];
__device__ float g_cA [2*NCH*D_];
__device__ float g_cB [2*NCH*D_];
__device__ float g_pref[2*NCH*D_];
__device__ float g_hbias[2][D_];        // layer0: bh + q0 @ Wh_bottom

__device__ __half g_xhi[T_*D_];                    // x hi (H-phase A operand)
__device__ __half g_uhi[T_*D_], g_ulo[T_*D_];      // u = x*q hi/lo (Z-phase)
__device__ __half g_qhi[T_*D_];                    // q hi (H-phase A operand)
__device__ __half g_wzT[5][D_*D_];      // [layerdir][n*256+k]
__device__ __half g_whT[5][D_*2*D_];    // [layerdir][n*512+k]

// ================= helpers =================
__device__ __forceinline__ uint32_t smem_u32(const void* p) {
    uint32_t a;
    asm("{ .reg .u64 t; cvta.to.shared.u64 t, %1; cvt.u32.u64 %0, t; }" : "=r"(a) : "l"(p));
    return a;
}
__device__ __forceinline__ void ldsm_x4(uint32_t (&r)[4], uint32_t addr) {
    asm volatile("ldmatrix.sync.aligned.m8n8.x4.shared.b16 {%0,%1,%2,%3}, [%4];"
                 : "=r"(r[0]), "=r"(r[1]), "=r"(r[2]), "=r"(r[3]) : "r"(addr));
}
__device__ __forceinline__ void mma16816(float (&d)[4], const uint32_t (&a)[4], const uint32_t* b) {
    asm volatile("mma.sync.aligned.m16n8k16.row.col.f32.f16.f16.f32 "
                 "{%0,%1,%2,%3}, {%4,%5,%6,%7}, {%8,%9}, {%0,%1,%2,%3};"
                 : "+f"(d[0]), "+f"(d[1]), "+f"(d[2]), "+f"(d[3])
                 : "r"(a[0]), "r"(a[1]), "r"(a[2]), "r"(a[3]), "r"(b[0]), "r"(b[1]));
}
__device__ __forceinline__ void cpa16(uint32_t dst, const void* src) {
    asm volatile("cp.async.cg.shared.global [%0], [%1], 16;" :: "r"(dst), "l"(src));
}
#define CP_COMMIT() asm volatile("cp.async.commit_group;" ::: "memory")
#define CP_WAIT1()  asm volatile("cp.async.wait_group 1;" ::: "memory")

__device__ __forceinline__ float sigf(float v)   { return 1.0f/(1.0f+__expf(-v)); }
__device__ __forceinline__ float tanhf_(float v) { return 1.0f - 2.0f/(__expf(2.0f*v)+1.0f); }
__device__ __forceinline__ void split2h(float v, __half& h, __half& l) {
    h = __float2half_rn(v);
    l = __float2half_rn(v - __half2float(h));
}

// ================= prep kernels =================
// ALL weight transposes in one launch: blockIdx.z encodes (ld, mz): z = ld*2 + mz
__global__ void prep_w(const float* __restrict__ Wz0, const float* __restrict__ Wh0,
                       const float* __restrict__ Wz1, const float* __restrict__ Wh1,
                       const float* __restrict__ Wz2, const float* __restrict__ Wh2,
                       const float* __restrict__ Wz3, const float* __restrict__ Wh3,
                       const float* __restrict__ Wz4, const float* __restrict__ Wh4)
{
    int ld = blockIdx.z >> 1, mz = blockIdx.z & 1;
    if (mz == 0 && blockIdx.y >= 8) return;
    const float* srcs[10] = {Wz0, Wh0, Wz1, Wh1, Wz2, Wh2, Wz3, Wh3, Wz4, Wh4};
    const float* src = srcs[blockIdx.z];
    int Krows = mz ? 512 : 256;
    __half* dh = mz ? &g_whT[ld][0] : &g_wzT[ld][0];
    int k0 = blockIdx.y*32, n0 = blockIdx.x*32;
    int tx = threadIdx.x, ty = threadIdx.y;
    __shared__ float t[32][33];
    #pragma unroll
    for (int i = 0; i < 4; i++)
        t[ty + i*8][tx] = src[(size_t)(k0 + ty + i*8)*256 + n0 + tx];
    __syncthreads();
    #pragma unroll
    for (int i = 0; i < 4; i++)
        dh[(size_t)(n0 + ty + i*8)*Krows + k0 + tx] = __float2half_rn(t[tx][ty + i*8]);
}

// x hi + u0 = x*q hi/lo (single story read)
__global__ void prep_xu(const float* __restrict__ story, const float* __restrict__ q)
{
    size_t i = ((size_t)blockIdx.x*256 + threadIdx.x)*2;
    int d = (int)(i & (D_-1));
    float2 v = *(const float2*)(story + i);
    __half2 ph;
    ph.x = __float2half_rn(v.x); ph.y = __float2half_rn(v.y);
    *(__half2*)(g_xhi+i) = ph;
    float u0 = v.x * q[d], u1 = v.y * q[d+1];
    __half h0,l0,h1,l1;
    split2h(u0,h0,l0); split2h(u1,h1,l1);
    __half2 pu, pl; pu.x=h0; pu.y=h1; pl.x=l0; pl.y=l1;
    *(__half2*)(g_uhi+i) = pu; *(__half2*)(g_ulo+i) = pl;
}

// warp-per-(dir,n): hbias[dir][n] = bh[n] + sum_k q[k]*Wh[(256+k)*256+n]
__global__ void qwh0(const float* __restrict__ Whf, const float* __restrict__ bhf,
                     const float* __restrict__ Whb, const float* __restrict__ bhb,
                     const float* __restrict__ q)
{
    int gw = (blockIdx.x * blockDim.x + threadIdx.x) >> 5;
    int lane = threadIdx.x & 31;
    int dir = gw >> 8, n = gw & 255;
    const float* Wh = dir ? Whb : Whf;
    const float* bh = dir ? bhb : bhf;
    float acc = 0.f;
    #pragma unroll
    for (int kk = 0; kk < 8; kk++) {
        int k = kk*32 + lane;
        acc = fmaf(q[k], Wh[(size_t)(256+k)*256 + n], acc);
    }
    #pragma unroll
    for (int o = 16; o; o >>= 1) acc += __shfl_xor_sync(0xFFFFFFFFu, acc, o);
    if (lane == 0) g_hbias[dir][n] = bh[n] + acc;
}

// ================= fused GEMM (mma.sync fp16, M=128 x N=64 tiles, 3 CTAs/SM) =================
// Z = [uhi; ulo] @ [Wz; Wz] (K-concat).
// Stage 15360B: A 128x32h (10240, 80B row pad) | B 64x32h (5120).
// 2-stage double buffer; strength-reduced issue (running pointers) + hoisted LDSM addrs.
// SMEM: [0,30720) stages | [30720,34816) pad | [34816,69632) zbuf fp32 128x68.
#define STAGE_B 15360
#define ZBUF_OFF 34816
#define SM_TOTAL 69632

__global__ __launch_bounds__(256, 3)
void qrn_gemm(int ld_f, int ld_b, int layer0, int store_ab,
              const float* __restrict__ bz_f_, const float* __restrict__ bz_b_,
              const float* __restrict__ bh_f_, const float* __restrict__ bh_b_)
{
    extern __shared__ __align__(16) char smem[];
    float* bbuf = (float*)smem;                      // aliases stages+pad post-mainloop
    float* zbuf = (float*)(smem + ZBUF_OFF);         // 128 x 68 fp32
    __shared__ float s_bz[64], s_bh[64];
    __shared__ float s_pA[4][64], s_pB[4][64];

    const int tid = threadIdx.x, lane = tid & 31, warp = tid >> 5;
    const int wm = warp & 3, wn = warp >> 2;         // 4M x 2N warps; warp tile 32x32
    const int ch = blockIdx.y;
    const int dir = blockIdx.z;
    const int ld = dir ? ld_b : ld_f;
    const int row0 = ch*CHUNK, n0g = blockIdx.x*64;
    const uint32_t base = smem_u32(smem);

    if (tid < 64) {
        s_bz[tid] = (dir ? bz_b_ : bz_f_)[n0g + tid];
        s_bh[tid] = layer0 ? g_hbias[dir][n0g + tid]
                           : (dir ? bh_b_ : bh_f_)[n0g + tid];
    }

    const __half* wz = &g_wzT[ld][0];
    const __half* wh = &g_whT[ld][0];
    const int S = layer0 ? 24 : 32;     // phases of 8: uhi@Wz, ulo@Wz, x@WhTop, q@WhBot

    // ---- thread-constant copy geometry ----
    const int rA = tid >> 2, qq = tid & 3;
    const uint32_t dstA0 = (uint32_t)(rA*80 + qq*16);
    const uint32_t dstA1 = dstA0 + 5120;             // rows 64..127
    const uint32_t dstB  = 10240 + dstA0;            // B rows 0..63

    // ---- hoisted LDSM lane offsets (bytes, within stage) ----
    uint32_t roff[2], boff[2];
    #pragma unroll
    for (int mi = 0; mi < 2; mi++)
        roff[mi] = (uint32_t)(wm*32 + mi*16 + (lane & 15))*80
                 + (uint32_t)(((lane >> 4) << 3)*2);
    #pragma unroll
    for (int pi = 0; pi < 2; pi++)
        boff[pi] = 10240
                 + (uint32_t)(wn*32 + pi*16 + ((lane >> 4) << 3) + (lane & 7))*80
                 + (uint32_t)((((lane >> 3) & 1) << 3)*2);

    // ---- running source pointers (reset per 8-step phase) ----
    const __half *pA0, *pA1, *pB;
    auto set_ptrs = [&](int s) {
        int ph = s >> 3, k = (s & 7)*32;
        const __half* Ab = (ph == 0) ? g_uhi : (ph == 1) ? g_ulo
                          : (ph == 2) ? g_xhi : g_qhi;
        pA0 = Ab + (size_t)(row0 + rA)*256 + k + qq*8;
        pA1 = Ab + (size_t)(row0 + 64 + rA)*256 + k + qq*8;
        if (ph < 2) pB = wz + (size_t)(n0g + rA)*256 + k + qq*8;
        else        pB = wh + (size_t)(n0g + rA)*512 + ((ph == 3) ? 256 : 0) + k + qq*8;
    };

    float acc[2][4][4];
    #pragma unroll
    for (int mi = 0; mi < 2; mi++)
        #pragma unroll
        for (int ni = 0; ni < 4; ni++)
            #pragma unroll
            for (int j = 0; j < 4; j++) acc[mi][ni][j] = 0.f;

    // prologue: issue stage 0; point at stage 1
    set_ptrs(0);
    cpa16(base + dstA0, pA0); cpa16(base + dstA1, pA1); cpa16(base + dstB, pB);
    CP_COMMIT();
    set_ptrs(1);

    for (int s = 0; s < S; s++) {
        __syncthreads();   // all warps done reading buffer (s+1)&1 (from iter s-1)
        if (s + 1 < S) {
            uint32_t sb = base + (uint32_t)(((s+1) & 1)*STAGE_B);
            cpa16(sb + dstA0, pA0); cpa16(sb + dstA1, pA1); cpa16(sb + dstB, pB);
            if (s + 2 < S) {
                if (((s + 2) & 7) == 0) set_ptrs(s + 2);
                else { pA0 += 32; pA1 += 32; pB += 32; }
            }
        }
        CP_COMMIT();
        CP_WAIT1();        // stage s arrived
        __syncthreads();

        {   // ---- mma step on stage s ----
            const uint32_t stg = base + (uint32_t)((s & 1)*STAGE_B);
            #pragma unroll
            for (int kk = 0; kk < 2; kk++) {
                const uint32_t kof = kk*32;     // 16 halves
                uint32_t aH[2][4], bb[4][2], t[4];
                ldsm_x4(aH[0], stg + roff[0] + kof);
                ldsm_x4(aH[1], stg + roff[1] + kof);
                ldsm_x4(t, stg + boff[0] + kof);
                bb[0][0]=t[0]; bb[0][1]=t[1]; bb[1][0]=t[2]; bb[1][1]=t[3];
                ldsm_x4(t, stg + boff[1] + kof);
                bb[2][0]=t[0]; bb[2][1]=t[1]; bb[3][0]=t[2]; bb[3][1]=t[3];
                #pragma unroll
                for (int mi = 0; mi < 2; mi++)
                    #pragma unroll
                    for (int ni = 0; ni < 4; ni++)
                        mma16816(acc[mi][ni], aH[mi], bb[ni]);
            }
        }

        if (s == 15) {     // z epilogue -> zbuf, reset acc for H phase
            #pragma unroll
            for (int mi = 0; mi < 2; mi++) {
                int r0 = wm*32 + mi*16 + (lane >> 2);
                #pragma unroll
                for (int ni = 0; ni < 4; ni++) {
                    int cl = wn*32 + ni*8 + (lane & 3)*2;
                    zbuf[r0*68 + cl]     = sigf(acc[mi][ni][0] + s_bz[cl]);
                    zbuf[r0*68 + cl + 1] = sigf(acc[mi][ni][1] + s_bz[cl+1]);
                    zbuf[(r0+8)*68 + cl]     = sigf(acc[mi][ni][2] + s_bz[cl]);
                    zbuf[(r0+8)*68 + cl + 1] = sigf(acc[mi][ni][3] + s_bz[cl+1]);
                    #pragma unroll
                    for (int j = 0; j < 4; j++) acc[mi][ni][j] = 0.f;
                }
            }
        }
    }
    __syncthreads();   // all MMA done; stage smem reusable as bbuf

    // ---- final epilogue: a = 1-z (into zbuf), b = z*tanh(h+bh) -> bbuf ----
    #pragma unroll
    for (int mi = 0; mi < 2; mi++) {
        int r0 = wm*32 + mi*16 + (lane >> 2);
        #pragma unroll
        for (int ni = 0; ni < 4; ni++) {
            int cl = wn*32 + ni*8 + (lane & 3)*2;
            #pragma unroll
            for (int hrow = 0; hrow < 2; hrow++) {
                int r = r0 + hrow*8;
                float z0 = zbuf[r*68 + cl], z1 = zbuf[r*68 + cl + 1];
                float h0 = tanhf_(acc[mi][ni][hrow*2+0] + s_bh[cl]);
                float h1 = tanhf_(acc[mi][ni][hrow*2+1] + s_bh[cl+1]);
                bbuf[r*68 + cl]     = z0*h0;
                bbuf[r*68 + cl + 1] = z1*h1;
                zbuf[r*68 + cl]     = 1.0f - z0;
                zbuf[r*68 + cl + 1] = 1.0f - z1;
            }
        }
    }
    __syncthreads();

    // ---- global a,b stores (128 rows x 64 cols) ----
    if (store_ab) {
        float* outA = dir ? g_ab2 : g_af;
        float* outB = dir ? g_bb2 : g_bf;
        #pragma unroll
        for (int i = 0; i < 8; i++) {
            int v = tid + i*256;          // 0..2047
            int r = v >> 4, c4 = (v & 15)*4;
            float4 va = *(float4*)(zbuf + r*68 + c4);
            float4 vb = *(float4*)(bbuf + r*68 + c4);
            size_t o = (size_t)(row0 + r)*256 + n0g + c4;
            *(float4*)(outA + o) = va;
            *(float4*)(outB + o) = vb;
        }
    }

    // ---- per-chunk scan composites (4 segs x 32 rows) ----
    {
        int cc = tid & 63, seg = tid >> 6;
        float pa = 1.0f, pb = 0.0f;
        if (dir == 0) {
            #pragma unroll 4
            for (int r = seg*32; r < seg*32 + 32; r++) {
                float a = zbuf[r*68 + cc], b = bbuf[r*68 + cc];
                pb = fmaf(a, pb, b); pa *= a;
            }
        } else {
            #pragma unroll 4
            for (int r = seg*32 + 31; r >= seg*32; r--) {
                float a = zbuf[r*68 + cc], b = bbuf[r*68 + cc];
                pb = fmaf(a, pb, b); pa *= a;
            }
        }
        s_pA[seg][cc] = pa; s_pB[seg][cc] = pb;
    }
    __syncthreads();
    if (tid < 64) {
        float A = 1.0f, B = 0.0f;
        if (dir == 0) {
            #pragma unroll
            for (int s = 0; s < 4; s++) { B = fmaf(s_pA[s][tid], B, s_pB[s][tid]); A *= s_pA[s][tid]; }
        } else {
            #pragma unroll
            for (int s = 3; s >= 0; s--) { B = fmaf(s_pA[s][tid], B, s_pB[s][tid]); A *= s_pA[s][tid]; }
        }
        size_t o = ((size_t)dir*NCH + ch)*256 + n0g + tid;
        g_cA[o] = A; g_cB[o] = B;
    }
}

// ================= scan kernels =================
__global__ __launch_bounds__(256) void scan_prefix()
{
    int dir = blockIdx.x, d = threadIdx.x;
    float cB = 0.f;
    if (dir == 0) {
        for (int c0 = 0; c0 < NCH; c0 += 8) {
            float a[8], b[8];
            #pragma unroll
            for (int i = 0; i < 8; i++) {
                a[i] = g_cA[(c0+i)*D_ + d];
                b[i] = g_cB[(c0+i)*D_ + d];
            }
            #pragma unroll
            for (int i = 0; i < 8; i++) {
                g_pref[(c0+i)*D_ + d] = cB;
                cB = fmaf(a[i], cB, b[i]);
            }
        }
    } else {
        for (int c0 = NCH - 8; c0 >= 0; c0 -= 8) {
            float a[8], b[8];
            #pragma unroll
            for (int i = 0; i < 8; i++) {
                a[i] = g_cA[(NCH + c0+i)*D_ + d];
                b[i] = g_cB[(NCH + c0+i)*D_ + d];
            }
            #pragma unroll
            for (int i = 7; i >= 0; i--) {
                g_pref[(NCH + c0+i)*D_ + d] = cB;
                cB = fmaf(a[i], cB, b[i]);
            }
        }
    }
}

// fused fwd+bwd apply + next-layer operand prep (h_fwd staged in smem)
__global__ __launch_bounds__(256) void scan_apply(const float* __restrict__ story)
{
    extern __shared__ float hbuf[];   // 128 x 256
    int d = threadIdx.x, ch = blockIdx.x;

    float h = g_pref[ch*D_ + d];
    size_t base = (size_t)ch*CHUNK*D_ + d;
    for (int j0 = 0; j0 < CHUNK; j0 += 8) {
        float a[8], b[8];
        #pragma unroll
        for (int i = 0; i < 8; i++) {
            size_t o = base + (size_t)(j0+i)*D_;
            a[i] = g_af[o]; b[i] = g_bf[o];
        }
        #pragma unroll
        for (int i = 0; i < 8; i++) {
            h = fmaf(a[i], h, b[i]);
            hbuf[(j0+i)*256 + d] = h;
        }
    }
    __syncthreads();

    float h2 = g_pref[(NCH + ch)*D_ + d];
    size_t base2 = ((size_t)ch*CHUNK + CHUNK-1)*D_ + d;
    for (int j0 = 0; j0 < CHUNK; j0 += 8) {
        float a[8], b[8], x[8];
        #pragma unroll
        for (int i = 0; i < 8; i++) {
            size_t o = base2 - (size_t)(j0+i)*D_;
            a[i] = g_ab2[o]; b[i] = g_bb2[o]; x[i] = story[o];
        }
        #pragma unroll
        for (int i = 0; i < 8; i++) {
            size_t o = base2 - (size_t)(j0+i)*D_;
            h2 = fmaf(a[i], h2, b[i]);
            float q = hbuf[(CHUNK-1-(j0+i))*256 + d] + h2;
            float u = x[i] * q;
            __half uh, ul;
            split2h(u, uh, ul);
            g_qhi[o] = __float2half_rn(q);
            g_uhi[o] = uh; g_ulo[o] = ul;
        }
    }
}

__global__ __launch_bounds__(256) void scan_final(float* __restrict__ out)
{
    int d = threadIdx.x;
    float cB = 0.f;
    for (int c0 = 0; c0 < NCH; c0 += 8) {
        float a[8], b[8];
        #pragma unroll
        for (int i = 0; i < 8; i++) {
            a[i] = g_cA[(c0+i)*D_ + d];
            b[i] = g_cB[(c0+i)*D_ + d];
        }
        #pragma unroll
        for (int i = 0; i < 8; i++)
            cB = fmaf(a[i], cB, b[i]);
    }
    out[d] = cB;
}

// ================= host launcher =================
extern "C" void kernel_launch(void* const* d_in, const int* in_sizes, int n_in,
                              void* d_out, int out_size)
{
    const float* story    = (const float*)d_in[0];
    const float* question = (const float*)d_in[1];
    const float* Wz_f     = (const float*)d_in[2];
    const float* bz_f     = (const float*)d_in[3];
    const float* Wh_f     = (const float*)d_in[4];
    const float* bh_f     = (const float*)d_in[5];
    const float* Wz_b     = (const float*)d_in[6];
    const float* bz_b     = (const float*)d_in[7];
    const float* Wh_b     = (const float*)d_in[8];
    const float* bh_b     = (const float*)d_in[9];
    float* out = (float*)d_out;

    cudaFuncSetAttribute(qrn_gemm,   cudaFuncAttributeMaxDynamicSharedMemorySize, SM_TOTAL);
    cudaFuncSetAttribute(scan_apply, cudaFuncAttributeMaxDynamicSharedMemorySize, 131072);

    // launch order: 3 predecessors then gemm at my-index 3 (ncu fixed window lands there)
    dim3 wb(32, 8), wg(8, 16, 10);
    prep_w<<<wg, wb>>>(Wz_f,           Wh_f,
                       Wz_b,           Wh_b,
                       Wz_f + 65536,   Wh_f + 131072,
                       Wz_b + 65536,   Wh_b + 131072,
                       Wz_f + 2*65536, Wh_f + 2*131072);
    prep_xu<<<T_*D_/512, 256>>>(story, question);
    qwh0<<<128, 128>>>(Wh_f, bh_f, Wh_b, bh_b, question);

    dim3 gg2(4, NCH, 2);   // (N-quarter, chunk, dir)
    dim3 gg1(4, NCH, 1);

    // ---- layer 0 (fwd+bwd merged) ----  <- my launch index 3: ncu capture target
    qrn_gemm<<<gg2, 256, SM_TOTAL>>>(0, 1, 1, 1, bz_f, bz_b, nullptr, nullptr);
    scan_prefix<<<2, 256>>>();
    scan_apply<<<NCH, 256, 131072>>>(story);

    // ---- layer 1 ----
    qrn_gemm<<<gg2, 256, SM_TOTAL>>>(2, 3, 0, 1, bz_f + 256, bz_b + 256, bh_f + 256, bh_b + 256);
    scan_prefix<<<2, 256>>>();
    scan_apply<<<NCH, 256, 131072>>>(story);

    // ---- layer 2 (forward only; composites only) ----
    qrn_gemm<<<gg1, 256, SM_TOTAL>>>(4, 4, 0, 0, bz_f + 512, bz_b + 512, bh_f + 512, bh_b + 512);
    scan_final<<<1, 256>>>(out);
}